// round 1
// baseline (speedup 1.0000x reference)
#include <cuda_runtime.h>
#include <math.h>

// Problem constants
#define LAYERS 63
#define BATCH  2048
#define BT     16      // batch elements per block
#define NTHREADS 256

// Shared memory layout (in floats)
#define S_W1    0        // 6*32 = 192
#define S_W2    192      // 96*64 = 6144
#define S_H1    6336     // 192 rows * 33 stride = 6336
#define S_ALLC  12672    // 192 rows * 97 stride = 18624 (reused as h2: 192*68=13056)
#define S_FW1   31296    // 128*64 = 8192
#define S_FW2   39488    // 64*64 = 4096
#define S_FW3   43584    // 64
#define S_FB1   43648    // 64
#define S_FB2   43712    // 64
#define S_FB3   43776    // 1
#define S_ZS    43777    // 16*12*2 = 384
#define SMEM_FLOATS 44161
#define SMEM_BYTES (SMEM_FLOATS * 4)

// reuse regions
#define S_POOL  S_H1                 // 16*128 = 2048
#define S_F1    (S_H1 + 2048)        // 16*65 = 1040
#define S_F2    (S_H1 + 3088)        // 16*65 = 1040
#define S_H2    S_ALLC               // 192 rows * 68 stride

__global__ void __launch_bounds__(NTHREADS, 1)
twelve_sites_kernel(const float* __restrict__ zs,
                    const float* __restrict__ w1,
                    const float* __restrict__ w2,
                    const float* __restrict__ fw1,
                    const float* __restrict__ fb1,
                    const float* __restrict__ fw2,
                    const float* __restrict__ fb2,
                    const float* __restrict__ fw3,
                    const float* __restrict__ fb3,
                    float* __restrict__ out)
{
    extern __shared__ float sm[];
    const int l    = blockIdx.y;          // layer
    const int b0   = blockIdx.x * BT;     // batch tile base
    const int tid  = threadIdx.x;

    // ------------------------------------------------------------------
    // Load all per-layer weights + zs tile into smem
    // ------------------------------------------------------------------
    for (int i = tid; i < 192; i += NTHREADS)  sm[S_W1 + i]  = w1[l * 192 + i];
    for (int i = tid; i < 6144; i += NTHREADS) sm[S_W2 + i]  = w2[l * 6144 + i];
    for (int i = tid; i < 8192; i += NTHREADS) sm[S_FW1 + i] = fw1[l * 8192 + i];
    for (int i = tid; i < 4096; i += NTHREADS) sm[S_FW2 + i] = fw2[l * 4096 + i];
    if (tid < 64) {
        sm[S_FW3 + tid] = fw3[l * 64 + tid];
        sm[S_FB1 + tid] = fb1[l * 64 + tid];
        sm[S_FB2 + tid] = fb2[l * 64 + tid];
    }
    if (tid == 0) sm[S_FB3] = fb3[l];
    // zs tile: zs[b][l][s][c], flat = (b*63 + l)*24 + s*2 + c
    for (int i = tid; i < BT * 24; i += NTHREADS) {
        int bt = i / 24;
        int rem = i % 24;
        sm[S_ZS + i] = zs[((size_t)(b0 + bt) * LAYERS + l) * 24 + rem];
    }
    __syncthreads();

    // ------------------------------------------------------------------
    // Phase A: CNN1  -> h1[192][32]  (row r = bt*12 + s, stride 33)
    // allc1 channels: [x0,x1, nn0,nn1, nnn0,nnn1]
    // ------------------------------------------------------------------
    if (tid < 192) {
        const int r  = tid;
        const int bt = r / 12;
        const int s  = r % 12;
        const float* xz = sm + S_ZS + bt * 24;
        const int sp1 = (s + 1) % 12, sm1 = (s + 11) % 12;
        const int sp2 = (s + 2) % 12, sm2 = (s + 10) % 12;
        const int sp3 = (s + 3) % 12, sm3 = (s + 9) % 12;
        const int sp4 = (s + 4) % 12, sm4 = (s + 8) % 12;
        float a0 = xz[s * 2 + 0];
        float a1 = xz[s * 2 + 1];
        float a2 = xz[sp1*2] + xz[sm1*2] + xz[sp3*2] + xz[sm3*2];
        float a3 = xz[sp1*2+1] + xz[sm1*2+1] + xz[sp3*2+1] + xz[sm3*2+1];
        float a4 = xz[sp2*2] + xz[sm2*2] + xz[sp4*2] + xz[sm4*2];
        float a5 = xz[sp2*2+1] + xz[sm2*2+1] + xz[sp4*2+1] + xz[sm4*2+1];
        float* hrow = sm + S_H1 + r * 33;
        const float* W = sm + S_W1;
        #pragma unroll
        for (int c = 0; c < 32; c++) {
            float v = a0 * W[c] + a1 * W[32 + c] + a2 * W[64 + c]
                    + a3 * W[96 + c] + a4 * W[128 + c] + a5 * W[160 + c];
            hrow[c] = fmaxf(v, 0.0f);
        }
    }
    __syncthreads();

    // ------------------------------------------------------------------
    // Phase A2: build allc2[192][96] (stride 97) from h1
    //  [0:32]  = h1[s]
    //  [32:64] = h1[s+1]+h1[s-1]+h1[s+3]+h1[s-3]
    //  [64:96] = h1[s+2]+h1[s-2]+h1[s+4]+h1[s-4]
    // ------------------------------------------------------------------
    if (tid < 192) {
        const int r    = tid;
        const int s    = r % 12;
        const int base = r - s;
        const float* h0  = sm + S_H1 + r * 33;
        const float* hp1 = sm + S_H1 + (base + (s + 1) % 12) * 33;
        const float* hm1 = sm + S_H1 + (base + (s + 11) % 12) * 33;
        const float* hp2 = sm + S_H1 + (base + (s + 2) % 12) * 33;
        const float* hm2 = sm + S_H1 + (base + (s + 10) % 12) * 33;
        const float* hp3 = sm + S_H1 + (base + (s + 3) % 12) * 33;
        const float* hm3 = sm + S_H1 + (base + (s + 9) % 12) * 33;
        const float* hp4 = sm + S_H1 + (base + (s + 4) % 12) * 33;
        const float* hm4 = sm + S_H1 + (base + (s + 8) % 12) * 33;
        float* arow = sm + S_ALLC + r * 97;
        #pragma unroll
        for (int j = 0; j < 32; j++) {
            arow[j]      = h0[j];
            arow[32 + j] = hp1[j] + hm1[j] + hp3[j] + hm3[j];
            arow[64 + j] = hp2[j] + hm2[j] + hp4[j] + hm4[j];
        }
    }
    __syncthreads();

    // ------------------------------------------------------------------
    // Phase B: CNN2 GEMM  C[192][64] = allc[192x96] @ w2[96x64], relu
    // thread micro-tile: 6 rows x 8 cols  (32 row-groups x 8 col-groups)
    // ------------------------------------------------------------------
    {
        const int rg = tid >> 3;     // 0..31
        const int cg = tid & 7;      // 0..7
        const float* A  = sm + S_ALLC + rg * 6 * 97;
        const float* Bw = sm + S_W2 + cg * 8;
        float acc[6][8];
        #pragma unroll
        for (int i = 0; i < 6; i++)
            #pragma unroll
            for (int j = 0; j < 8; j++) acc[i][j] = 0.0f;

        #pragma unroll 4
        for (int k = 0; k < 96; k++) {
            float4 bv0 = *(const float4*)(Bw + k * 64);
            float4 bv1 = *(const float4*)(Bw + k * 64 + 4);
            #pragma unroll
            for (int i = 0; i < 6; i++) {
                float a = A[i * 97 + k];
                acc[i][0] += a * bv0.x;
                acc[i][1] += a * bv0.y;
                acc[i][2] += a * bv0.z;
                acc[i][3] += a * bv0.w;
                acc[i][4] += a * bv1.x;
                acc[i][5] += a * bv1.y;
                acc[i][6] += a * bv1.z;
                acc[i][7] += a * bv1.w;
            }
        }
        __syncthreads();   // all reads of allc done before overwriting with h2

        #pragma unroll
        for (int i = 0; i < 6; i++) {
            float* dst = sm + S_H2 + (rg * 6 + i) * 68 + cg * 8;
            float4 v0, v1;
            v0.x = fmaxf(acc[i][0], 0.f); v0.y = fmaxf(acc[i][1], 0.f);
            v0.z = fmaxf(acc[i][2], 0.f); v0.w = fmaxf(acc[i][3], 0.f);
            v1.x = fmaxf(acc[i][4], 0.f); v1.y = fmaxf(acc[i][5], 0.f);
            v1.z = fmaxf(acc[i][6], 0.f); v1.w = fmaxf(acc[i][7], 0.f);
            *(float4*)(dst)     = v0;
            *(float4*)(dst + 4) = v1;
        }
    }
    __syncthreads();

    // ------------------------------------------------------------------
    // Phase C1: pool over sites -> pooled[16][128] = [mean(64) | max(64)]
    // (pool lives in the now-dead h1 region)
    // ------------------------------------------------------------------
    for (int idx = tid; idx < BT * 64; idx += NTHREADS) {
        int bt = idx >> 6;
        int o  = idx & 63;
        const float* p = sm + S_H2 + bt * 12 * 68 + o;
        float s0 = p[0];
        float sum = s0, mx = s0;
        #pragma unroll
        for (int s = 1; s < 12; s++) {
            float v = p[s * 68];
            sum += v;
            mx = fmaxf(mx, v);
        }
        sm[S_POOL + bt * 128 + o]      = sum * (1.0f / 12.0f);
        sm[S_POOL + bt * 128 + 64 + o] = mx;
    }
    __syncthreads();

    // ------------------------------------------------------------------
    // Phase C2: fc1 (128->64) + relu.  thread: (btg = tid>>6, o = tid&63),
    // handles bt = btg, btg+4, btg+8, btg+12
    // ------------------------------------------------------------------
    {
        const int o   = tid & 63;
        const int btg = tid >> 6;
        float acc[4];
        #pragma unroll
        for (int ii = 0; ii < 4; ii++) acc[ii] = sm[S_FB1 + o];
        #pragma unroll 4
        for (int f = 0; f < 128; f++) {
            float w = sm[S_FW1 + f * 64 + o];
            #pragma unroll
            for (int ii = 0; ii < 4; ii++)
                acc[ii] += sm[S_POOL + (btg + 4 * ii) * 128 + f] * w;
        }
        #pragma unroll
        for (int ii = 0; ii < 4; ii++)
            sm[S_F1 + (btg + 4 * ii) * 65 + o] = fmaxf(acc[ii], 0.0f);
    }
    __syncthreads();

    // Phase C3: fc2 (64->64) + relu
    {
        const int o   = tid & 63;
        const int btg = tid >> 6;
        float acc[4];
        #pragma unroll
        for (int ii = 0; ii < 4; ii++) acc[ii] = sm[S_FB2 + o];
        #pragma unroll 4
        for (int k = 0; k < 64; k++) {
            float w = sm[S_FW2 + k * 64 + o];
            #pragma unroll
            for (int ii = 0; ii < 4; ii++)
                acc[ii] += sm[S_F1 + (btg + 4 * ii) * 65 + k] * w;
        }
        #pragma unroll
        for (int ii = 0; ii < 4; ii++)
            sm[S_F2 + (btg + 4 * ii) * 65 + o] = fmaxf(acc[ii], 0.0f);
    }
    __syncthreads();

    // Phase C4: fc3 (64->1) + output (B, L) row-major
    if (tid < BT) {
        const int bt = tid;
        const float* f2 = sm + S_F2 + bt * 65;
        float acc = sm[S_FB3];
        #pragma unroll
        for (int k = 0; k < 64; k++) acc += f2[k] * sm[S_FW3 + k];
        out[(size_t)(b0 + bt) * LAYERS + l] = acc;
    }
}

extern "C" void kernel_launch(void* const* d_in, const int* in_sizes, int n_in,
                              void* d_out, int out_size)
{
    (void)in_sizes; (void)n_in; (void)out_size;
    const float* zs  = (const float*)d_in[0];
    const float* w1  = (const float*)d_in[1];
    const float* w2  = (const float*)d_in[2];
    const float* fw1 = (const float*)d_in[3];
    const float* fb1 = (const float*)d_in[4];
    const float* fw2 = (const float*)d_in[5];
    const float* fb2 = (const float*)d_in[6];
    const float* fw3 = (const float*)d_in[7];
    const float* fb3 = (const float*)d_in[8];
    float* out = (float*)d_out;

    static bool attr_set = false;
    if (!attr_set) {
        cudaFuncSetAttribute(twelve_sites_kernel,
                             cudaFuncAttributeMaxDynamicSharedMemorySize,
                             SMEM_BYTES);
        attr_set = true;
    }

    dim3 grid(BATCH / BT, LAYERS);   // (128, 63)
    twelve_sites_kernel<<<grid, NTHREADS, SMEM_BYTES>>>(
        zs, w1, w2, fw1, fb1, fw2, fb2, fw3, fb3, out);
}

// round 2
// speedup vs baseline: 1.4924x; 1.4924x over previous
#include <cuda_runtime.h>
#include <math.h>

// Problem constants
#define LAYERS 63
#define BATCH  2048
#define BT     32          // batch elements per block
#define NTHREADS 512
#define ROWS   (BT * 12)   // 384

// ---------------- shared memory layout (floats) ----------------
#define S_W1    0          // 6*32 = 192
#define S_ZS    192        // 32*24 = 768          -> 960
#define S_FB1   960        // 64
#define S_FB2   1024       // 64
#define S_FW3   1088       // 64
#define S_FB3   1152       // 1                    -> 1153 (pad to 1184)
#define S_H1    1184       // 384 rows * 36 = 13824 -> 15008
#define S_W2    15008      // 96*64 = 6144          -> 21152
#define S_G     21152      // 384 rows * 68 = 26112 -> 47264
#define SMEM_FLOATS 47264
#define SMEM_BYTES (SMEM_FLOATS * 4)   // 189,056 B

// post-phase-B aliases (regions dead by then)
#define S_FW1   S_H1             // 8192  (h1 dead after GEMM)
#define S_FW2   (S_H1 + 8192)    // 4096  -> ends 13472 <= 15008
#define S_POOL  S_W2             // 32*128 = 4096 (w2 dead after GEMM)
#define S_H2    S_G              // 384 rows * 68 (g dead after GEMM accumulate)
#define S_F1    S_G              // 32*65 = 2080 (h2 dead after pool)
#define S_F2    (S_G + 2080)     // 2080

// packed dual-fp32 FMA (Blackwell FFMA2)
__device__ __forceinline__ void fma2(unsigned long long& d,
                                     unsigned long long a,
                                     unsigned long long b) {
    asm("fma.rn.f32x2 %0, %1, %2, %0;" : "+l"(d) : "l"(a), "l"(b));
}
__device__ __forceinline__ unsigned long long pk(float a) {
    unsigned long long r;
    asm("mov.b64 %0, {%1, %1};" : "=l"(r) : "f"(a));
    return r;
}
__device__ __forceinline__ void unpk(unsigned long long v, float& lo, float& hi) {
    asm("mov.b64 {%0, %1}, %2;" : "=f"(lo), "=f"(hi) : "l"(v));
}

__global__ void __launch_bounds__(NTHREADS, 1)
twelve_sites_kernel(const float* __restrict__ zs,
                    const float* __restrict__ w1,
                    const float* __restrict__ w2,
                    const float* __restrict__ fw1,
                    const float* __restrict__ fb1,
                    const float* __restrict__ fw2,
                    const float* __restrict__ fb2,
                    const float* __restrict__ fw3,
                    const float* __restrict__ fb3,
                    float* __restrict__ out)
{
    extern __shared__ float sm[];
    const int l   = blockIdx.y;
    const int b0  = blockIdx.x * BT;
    const int tid = threadIdx.x;

    // ------------------------------------------------------------------
    // Load phase-A/B weights + zs tile
    // ------------------------------------------------------------------
    for (int i = tid; i < 192; i += NTHREADS) sm[S_W1 + i] = w1[l * 192 + i];
    {
        const float4* w2v = (const float4*)(w2 + (size_t)l * 6144);
        for (int i = tid; i < 1536; i += NTHREADS)
            *(float4*)(sm + S_W2 + i * 4) = w2v[i];
    }
    if (tid < 64) {
        sm[S_FB1 + tid] = fb1[l * 64 + tid];
        sm[S_FB2 + tid] = fb2[l * 64 + tid];
        sm[S_FW3 + tid] = fw3[l * 64 + tid];
    }
    if (tid == 0) sm[S_FB3] = fb3[l];
    for (int i = tid; i < BT * 24; i += NTHREADS) {
        int bt = i / 24;
        int rem = i % 24;
        sm[S_ZS + i] = zs[((size_t)(b0 + bt) * LAYERS + l) * 24 + rem];
    }
    __syncthreads();

    // ------------------------------------------------------------------
    // Phase A: CNN1 -> h1[384][32] (stride 36)
    // ------------------------------------------------------------------
    if (tid < ROWS) {
        const int r  = tid;
        const int bt = r / 12;
        const int s  = r % 12;
        const float* xz = sm + S_ZS + bt * 24;
        const int sp1 = (s + 1) % 12, sm1 = (s + 11) % 12;
        const int sp2 = (s + 2) % 12, sm2 = (s + 10) % 12;
        const int sp3 = (s + 3) % 12, sm3 = (s + 9) % 12;
        const int sp4 = (s + 4) % 12, sm4 = (s + 8) % 12;
        float a0 = xz[s * 2 + 0];
        float a1 = xz[s * 2 + 1];
        float a2 = xz[sp1*2]   + xz[sm1*2]   + xz[sp3*2]   + xz[sm3*2];
        float a3 = xz[sp1*2+1] + xz[sm1*2+1] + xz[sp3*2+1] + xz[sm3*2+1];
        float a4 = xz[sp2*2]   + xz[sm2*2]   + xz[sp4*2]   + xz[sm4*2];
        float a5 = xz[sp2*2+1] + xz[sm2*2+1] + xz[sp4*2+1] + xz[sm4*2+1];
        float* hrow = sm + S_H1 + r * 36;
        const float* W = sm + S_W1;
        #pragma unroll
        for (int c4 = 0; c4 < 8; c4++) {
            float4 v;
            #pragma unroll
            for (int cc = 0; cc < 4; cc++) {
                int c = c4 * 4 + cc;
                float t = a0 * W[c] + a1 * W[32 + c] + a2 * W[64 + c]
                        + a3 * W[96 + c] + a4 * W[128 + c] + a5 * W[160 + c];
                (&v.x)[cc] = fmaxf(t, 0.0f);
            }
            *(float4*)(hrow + c4 * 4) = v;
        }
    }
    __syncthreads();

    // ------------------------------------------------------------------
    // Phase A2: g[384][64] (stride 68): [0:32]=p1+m1+p3+m3, [32:64]=p2+m2+p4+m4
    // ------------------------------------------------------------------
    if (tid < ROWS) {
        const int r    = tid;
        const int s    = r % 12;
        const int base = r - s;
        const float4* hp1 = (const float4*)(sm + S_H1 + (base + (s + 1) % 12) * 36);
        const float4* hm1 = (const float4*)(sm + S_H1 + (base + (s + 11) % 12) * 36);
        const float4* hp2 = (const float4*)(sm + S_H1 + (base + (s + 2) % 12) * 36);
        const float4* hm2 = (const float4*)(sm + S_H1 + (base + (s + 10) % 12) * 36);
        const float4* hp3 = (const float4*)(sm + S_H1 + (base + (s + 3) % 12) * 36);
        const float4* hm3 = (const float4*)(sm + S_H1 + (base + (s + 9) % 12) * 36);
        const float4* hp4 = (const float4*)(sm + S_H1 + (base + (s + 4) % 12) * 36);
        const float4* hm4 = (const float4*)(sm + S_H1 + (base + (s + 8) % 12) * 36);
        float* grow = sm + S_G + r * 68;
        #pragma unroll
        for (int j4 = 0; j4 < 8; j4++) {
            float4 p1 = hp1[j4], m1 = hm1[j4], p3 = hp3[j4], m3 = hm3[j4];
            float4 p2 = hp2[j4], m2 = hm2[j4], p4 = hp4[j4], m4 = hm4[j4];
            float4 g1, g2;
            g1.x = p1.x + m1.x + p3.x + m3.x;  g1.y = p1.y + m1.y + p3.y + m3.y;
            g1.z = p1.z + m1.z + p3.z + m3.z;  g1.w = p1.w + m1.w + p3.w + m3.w;
            g2.x = p2.x + m2.x + p4.x + m4.x;  g2.y = p2.y + m2.y + p4.y + m4.y;
            g2.z = p2.z + m2.z + p4.z + m4.z;  g2.w = p2.w + m2.w + p4.w + m4.w;
            *(float4*)(grow + j4 * 4)      = g1;
            *(float4*)(grow + 32 + j4 * 4) = g2;
        }
    }
    __syncthreads();

    // ------------------------------------------------------------------
    // Phase B: GEMM  h2[384][64] = [h1 | g] @ w2[96][64], relu.
    // thread tile 6 rows x 8 cols; FFMA2 packs cols in pairs.
    // ------------------------------------------------------------------
    {
        const int rg = tid >> 3;     // 0..63
        const int cg = tid & 7;      // 0..7
        const float* Ah = sm + S_H1 + rg * 6 * 36;
        const float* Ag = sm + S_G  + rg * 6 * 68;
        const float* Bw = sm + S_W2 + cg * 8;

        unsigned long long acc[6][4];
        #pragma unroll
        for (int i = 0; i < 6; i++)
            #pragma unroll
            for (int j = 0; j < 4; j++) acc[i][j] = 0ull;

        // segment 0: k = 0..31 from h1
        #pragma unroll 2
        for (int k4 = 0; k4 < 8; k4++) {
            float4 a4[6];
            #pragma unroll
            for (int i = 0; i < 6; i++)
                a4[i] = *(const float4*)(Ah + i * 36 + k4 * 4);
            #pragma unroll
            for (int kk = 0; kk < 4; kk++) {
                const float* bk = Bw + (k4 * 4 + kk) * 64;
                ulonglong2 bA = *(const ulonglong2*)(bk);
                ulonglong2 bB = *(const ulonglong2*)(bk + 4);
                #pragma unroll
                for (int i = 0; i < 6; i++) {
                    unsigned long long aa = pk((&a4[i].x)[kk]);
                    fma2(acc[i][0], aa, bA.x);
                    fma2(acc[i][1], aa, bA.y);
                    fma2(acc[i][2], aa, bB.x);
                    fma2(acc[i][3], aa, bB.y);
                }
            }
        }
        // segments 1+2: k = 32..95 from g
        #pragma unroll 2
        for (int k4 = 0; k4 < 16; k4++) {
            float4 a4[6];
            #pragma unroll
            for (int i = 0; i < 6; i++)
                a4[i] = *(const float4*)(Ag + i * 68 + k4 * 4);
            #pragma unroll
            for (int kk = 0; kk < 4; kk++) {
                const float* bk = Bw + (32 + k4 * 4 + kk) * 64;
                ulonglong2 bA = *(const ulonglong2*)(bk);
                ulonglong2 bB = *(const ulonglong2*)(bk + 4);
                #pragma unroll
                for (int i = 0; i < 6; i++) {
                    unsigned long long aa = pk((&a4[i].x)[kk]);
                    fma2(acc[i][0], aa, bA.x);
                    fma2(acc[i][1], aa, bA.y);
                    fma2(acc[i][2], aa, bB.x);
                    fma2(acc[i][3], aa, bB.y);
                }
            }
        }
        __syncthreads();   // all reads of h1/g/w2 complete

        // store h2 (relu) into g region
        #pragma unroll
        for (int i = 0; i < 6; i++) {
            float* dst = sm + S_H2 + (rg * 6 + i) * 68 + cg * 8;
            float4 v0, v1;
            unpk(acc[i][0], v0.x, v0.y);
            unpk(acc[i][1], v0.z, v0.w);
            unpk(acc[i][2], v1.x, v1.y);
            unpk(acc[i][3], v1.z, v1.w);
            v0.x = fmaxf(v0.x, 0.f); v0.y = fmaxf(v0.y, 0.f);
            v0.z = fmaxf(v0.z, 0.f); v0.w = fmaxf(v0.w, 0.f);
            v1.x = fmaxf(v1.x, 0.f); v1.y = fmaxf(v1.y, 0.f);
            v1.z = fmaxf(v1.z, 0.f); v1.w = fmaxf(v1.w, 0.f);
            *(float4*)(dst)     = v0;
            *(float4*)(dst + 4) = v1;
        }
    }

    // deferred FW1/FW2 load into the (now dead) h1/w2-front region.
    // S_FW2 == S_FW1 + 8192 so the two arrays are contiguous in smem.
    {
        const float4* f1v = (const float4*)(fw1 + (size_t)l * 8192);
        const float4* f2v = (const float4*)(fw2 + (size_t)l * 4096);
        #pragma unroll
        for (int j = 0; j < 6; j++) {
            int i = tid + j * NTHREADS;        // 0..3071
            float4 v = (i < 2048) ? f1v[i] : f2v[i - 2048];
            *(float4*)(sm + S_FW1 + i * 4) = v;
        }
    }
    __syncthreads();

    // ------------------------------------------------------------------
    // Pool: pooled[32][128] = [mean(64) | max(64)] over 12 sites
    // ------------------------------------------------------------------
    #pragma unroll
    for (int p = 0; p < (BT * 64) / NTHREADS; p++) {
        int idx = tid + p * NTHREADS;
        int bt = idx >> 6;
        int o  = idx & 63;
        const float* q = sm + S_H2 + bt * 12 * 68 + o;
        float v0 = q[0];
        float sum = v0, mx = v0;
        #pragma unroll
        for (int s = 1; s < 12; s++) {
            float v = q[s * 68];
            sum += v;
            mx = fmaxf(mx, v);
        }
        sm[S_POOL + bt * 128 + o]      = sum * (1.0f / 12.0f);
        sm[S_POOL + bt * 128 + 64 + o] = mx;
    }
    __syncthreads();

    // ------------------------------------------------------------------
    // fc1 (128->64) + relu : o = tid&63, btg = tid>>6 handles 4 batches
    // ------------------------------------------------------------------
    {
        const int o   = tid & 63;
        const int btg = tid >> 6;        // 0..7
        float acc[4];
        #pragma unroll
        for (int ii = 0; ii < 4; ii++) acc[ii] = sm[S_FB1 + o];
        #pragma unroll 4
        for (int f = 0; f < 128; f++) {
            float w = sm[S_FW1 + f * 64 + o];
            #pragma unroll
            for (int ii = 0; ii < 4; ii++)
                acc[ii] += sm[S_POOL + (btg + 8 * ii) * 128 + f] * w;
        }
        __syncthreads();   // h2 reads (pool) done before f1 overwrites that region
        #pragma unroll
        for (int ii = 0; ii < 4; ii++)
            sm[S_F1 + (btg + 8 * ii) * 65 + o] = fmaxf(acc[ii], 0.0f);
    }
    __syncthreads();

    // fc2 (64->64) + relu
    {
        const int o   = tid & 63;
        const int btg = tid >> 6;
        float acc[4];
        #pragma unroll
        for (int ii = 0; ii < 4; ii++) acc[ii] = sm[S_FB2 + o];
        #pragma unroll 4
        for (int k = 0; k < 64; k++) {
            float w = sm[S_FW2 + k * 64 + o];
            #pragma unroll
            for (int ii = 0; ii < 4; ii++)
                acc[ii] += sm[S_F1 + (btg + 8 * ii) * 65 + k] * w;
        }
        #pragma unroll
        for (int ii = 0; ii < 4; ii++)
            sm[S_F2 + (btg + 8 * ii) * 65 + o] = fmaxf(acc[ii], 0.0f);
    }
    __syncthreads();

    // fc3 (64->1), out is (B, L) row-major
    if (tid < BT) {
        const int bt = tid;
        const float* f2 = sm + S_F2 + bt * 65;
        float acc = sm[S_FB3];
        #pragma unroll
        for (int k = 0; k < 64; k++) acc += f2[k] * sm[S_FW3 + k];
        out[(size_t)(b0 + bt) * LAYERS + l] = acc;
    }
}

extern "C" void kernel_launch(void* const* d_in, const int* in_sizes, int n_in,
                              void* d_out, int out_size)
{
    (void)in_sizes; (void)n_in; (void)out_size;
    const float* zs  = (const float*)d_in[0];
    const float* w1  = (const float*)d_in[1];
    const float* w2  = (const float*)d_in[2];
    const float* fw1 = (const float*)d_in[3];
    const float* fb1 = (const float*)d_in[4];
    const float* fw2 = (const float*)d_in[5];
    const float* fb2 = (const float*)d_in[6];
    const float* fw3 = (const float*)d_in[7];
    const float* fb3 = (const float*)d_in[8];
    float* out = (float*)d_out;

    static bool attr_set = false;
    if (!attr_set) {
        cudaFuncSetAttribute(twelve_sites_kernel,
                             cudaFuncAttributeMaxDynamicSharedMemorySize,
                             SMEM_BYTES);
        attr_set = true;
    }

    dim3 grid(BATCH / BT, LAYERS);   // (64, 63)
    twelve_sites_kernel<<<grid, NTHREADS, SMEM_BYTES>>>(
        zs, w1, w2, fw1, fb1, fw2, fb2, fw3, fb3, out);
}

// round 3
// speedup vs baseline: 1.6228x; 1.0874x over previous
#include <cuda_runtime.h>
#include <math.h>

// Problem constants
#define LAYERS 63
#define BATCH  2048
#define BT     32          // batch elements per block
#define NTHREADS 512
#define ROWS   (BT * 12)   // 384

// ---------------- shared memory layout (floats) ----------------
#define S_W1    0          // 6*32 = 192
#define S_ZS    192        // 32*24 = 768          -> 960
#define S_FB1   960        // 64
#define S_FB2   1024       // 64
#define S_FW3   1088       // 64
#define S_FB3   1152       // 1                    -> pad to 1184
#define S_H1    1184       // 384 rows * 36 = 13824 -> 15008
#define S_W2    15008      // 96*64 = 6144          -> 21152
#define S_G     21152      // 384 rows * 68 = 26112 -> 47264
#define SMEM_FLOATS 47264
#define SMEM_BYTES (SMEM_FLOATS * 4)   // 189,056 B

// post-phase-B aliases (regions dead by then)
#define S_FW1   S_H1             // 8192  (h1 dead after GEMM)
#define S_FW2   (S_H1 + 8192)    // 4096  -> ends 13472 <= 15008
#define S_POOL  S_W2             // 32*128 = 4096 (w2 dead after GEMM)
#define S_H2    S_G              // 384 rows * 68 (g dead after GEMM accumulate)
#define S_F1    S_G              // 32*68 = 2176 (h2 dead after pool)
#define S_F2    (S_G + 2176)     // 2176

// packed dual-fp32 FMA (Blackwell FFMA2)
__device__ __forceinline__ void fma2(unsigned long long& d,
                                     unsigned long long a,
                                     unsigned long long b) {
    asm("fma.rn.f32x2 %0, %1, %2, %0;" : "+l"(d) : "l"(a), "l"(b));
}
__device__ __forceinline__ unsigned long long pk(float a) {
    unsigned long long r;
    asm("mov.b64 %0, {%1, %1};" : "=l"(r) : "f"(a));
    return r;
}
__device__ __forceinline__ unsigned long long pk2(float lo, float hi) {
    unsigned long long r;
    asm("mov.b64 %0, {%1, %2};" : "=l"(r) : "f"(lo), "f"(hi));
    return r;
}
__device__ __forceinline__ void unpk(unsigned long long v, float& lo, float& hi) {
    asm("mov.b64 {%0, %1}, %2;" : "=f"(lo), "=f"(hi) : "l"(v));
}

__global__ void __launch_bounds__(NTHREADS, 1)
twelve_sites_kernel(const float* __restrict__ zs,
                    const float* __restrict__ w1,
                    const float* __restrict__ w2,
                    const float* __restrict__ fw1,
                    const float* __restrict__ fb1,
                    const float* __restrict__ fw2,
                    const float* __restrict__ fb2,
                    const float* __restrict__ fw3,
                    const float* __restrict__ fb3,
                    float* __restrict__ out)
{
    extern __shared__ float sm[];
    const int l   = blockIdx.y;
    const int b0  = blockIdx.x * BT;
    const int tid = threadIdx.x;

    // ------------------------------------------------------------------
    // Load phase-A/B weights + zs tile
    // ------------------------------------------------------------------
    for (int i = tid; i < 192; i += NTHREADS) sm[S_W1 + i] = w1[l * 192 + i];
    {
        const float4* w2v = (const float4*)(w2 + (size_t)l * 6144);
        for (int i = tid; i < 1536; i += NTHREADS)
            *(float4*)(sm + S_W2 + i * 4) = w2v[i];
    }
    if (tid < 64) {
        sm[S_FB1 + tid] = fb1[l * 64 + tid];
        sm[S_FB2 + tid] = fb2[l * 64 + tid];
        sm[S_FW3 + tid] = fw3[l * 64 + tid];
    }
    if (tid == 0) sm[S_FB3] = fb3[l];
    // zs tile: 24 contiguous floats per (b); 16B-aligned (96B rows)
    for (int i = tid; i < BT * 6; i += NTHREADS) {
        int bt = i / 6;
        int j  = i % 6;
        *(float4*)(sm + S_ZS + bt * 24 + j * 4) =
            *(const float4*)(zs + ((size_t)(b0 + bt) * LAYERS + l) * 24 + j * 4);
    }
    __syncthreads();

    // ------------------------------------------------------------------
    // Phase A: CNN1 -> h1[384][36-stride], vectorized W1 reads
    // ------------------------------------------------------------------
    if (tid < ROWS) {
        const int r  = tid;
        const int bt = r / 12;
        const int s  = r % 12;
        const float* xz = sm + S_ZS + bt * 24;
        const int sp1 = (s + 1) % 12, sm1 = (s + 11) % 12;
        const int sp2 = (s + 2) % 12, sm2 = (s + 10) % 12;
        const int sp3 = (s + 3) % 12, sm3 = (s + 9) % 12;
        const int sp4 = (s + 4) % 12, sm4 = (s + 8) % 12;
        float a0 = xz[s * 2 + 0];
        float a1 = xz[s * 2 + 1];
        float a2 = xz[sp1*2]   + xz[sm1*2]   + xz[sp3*2]   + xz[sm3*2];
        float a3 = xz[sp1*2+1] + xz[sm1*2+1] + xz[sp3*2+1] + xz[sm3*2+1];
        float a4 = xz[sp2*2]   + xz[sm2*2]   + xz[sp4*2]   + xz[sm4*2];
        float a5 = xz[sp2*2+1] + xz[sm2*2+1] + xz[sp4*2+1] + xz[sm4*2+1];
        float* hrow = sm + S_H1 + r * 36;
        const float4* W4 = (const float4*)(sm + S_W1);   // [6][8] float4
        #pragma unroll
        for (int c4 = 0; c4 < 8; c4++) {
            float4 q0 = W4[c4],      q1 = W4[8 + c4],  q2 = W4[16 + c4];
            float4 q3 = W4[24 + c4], q4 = W4[32 + c4], q5 = W4[40 + c4];
            float4 v;
            v.x = fmaxf(a0*q0.x + a1*q1.x + a2*q2.x + a3*q3.x + a4*q4.x + a5*q5.x, 0.f);
            v.y = fmaxf(a0*q0.y + a1*q1.y + a2*q2.y + a3*q3.y + a4*q4.y + a5*q5.y, 0.f);
            v.z = fmaxf(a0*q0.z + a1*q1.z + a2*q2.z + a3*q3.z + a4*q4.z + a5*q5.z, 0.f);
            v.w = fmaxf(a0*q0.w + a1*q1.w + a2*q2.w + a3*q3.w + a4*q4.w + a5*q5.w, 0.f);
            *(float4*)(hrow + c4 * 4) = v;
        }
    }
    __syncthreads();

    // ------------------------------------------------------------------
    // Phase A2: g[384][68-stride]: [0:32]=p1+m1+p3+m3, [32:64]=p2+m2+p4+m4
    // ------------------------------------------------------------------
    if (tid < ROWS) {
        const int r    = tid;
        const int s    = r % 12;
        const int base = r - s;
        const float4* hp1 = (const float4*)(sm + S_H1 + (base + (s + 1) % 12) * 36);
        const float4* hm1 = (const float4*)(sm + S_H1 + (base + (s + 11) % 12) * 36);
        const float4* hp2 = (const float4*)(sm + S_H1 + (base + (s + 2) % 12) * 36);
        const float4* hm2 = (const float4*)(sm + S_H1 + (base + (s + 10) % 12) * 36);
        const float4* hp3 = (const float4*)(sm + S_H1 + (base + (s + 3) % 12) * 36);
        const float4* hm3 = (const float4*)(sm + S_H1 + (base + (s + 9) % 12) * 36);
        const float4* hp4 = (const float4*)(sm + S_H1 + (base + (s + 4) % 12) * 36);
        const float4* hm4 = (const float4*)(sm + S_H1 + (base + (s + 8) % 12) * 36);
        float* grow = sm + S_G + r * 68;
        #pragma unroll
        for (int j4 = 0; j4 < 8; j4++) {
            float4 p1 = hp1[j4], m1 = hm1[j4], p3 = hp3[j4], m3 = hm3[j4];
            float4 p2 = hp2[j4], m2 = hm2[j4], p4 = hp4[j4], m4 = hm4[j4];
            float4 g1, g2;
            g1.x = p1.x + m1.x + p3.x + m3.x;  g1.y = p1.y + m1.y + p3.y + m3.y;
            g1.z = p1.z + m1.z + p3.z + m3.z;  g1.w = p1.w + m1.w + p3.w + m3.w;
            g2.x = p2.x + m2.x + p4.x + m4.x;  g2.y = p2.y + m2.y + p4.y + m4.y;
            g2.z = p2.z + m2.z + p4.z + m4.z;  g2.w = p2.w + m2.w + p4.w + m4.w;
            *(float4*)(grow + j4 * 4)      = g1;
            *(float4*)(grow + 32 + j4 * 4) = g2;
        }
    }
    __syncthreads();

    // ------------------------------------------------------------------
    // Phase B: GEMM  h2[384][64] = [h1 | g] @ w2[96][64], relu.
    // thread tile 6 rows x cols {cg*4..+3, 32+cg*4..+3} (conflict-free B)
    // ------------------------------------------------------------------
    {
        const int rg = tid >> 3;     // 0..63
        const int cg = tid & 7;      // 0..7
        const float* Ah = sm + S_H1 + rg * 6 * 36;
        const float* Ag = sm + S_G  + rg * 6 * 68;
        const float* BwA = sm + S_W2 + cg * 4;        // cols cg*4..+3
        const float* BwB = sm + S_W2 + 32 + cg * 4;   // cols 32+cg*4..+3

        unsigned long long acc[6][4];
        #pragma unroll
        for (int i = 0; i < 6; i++)
            #pragma unroll
            for (int j = 0; j < 4; j++) acc[i][j] = 0ull;

        // segment 0: k = 0..31 from h1
        #pragma unroll 2
        for (int k4 = 0; k4 < 8; k4++) {
            float4 a4[6];
            #pragma unroll
            for (int i = 0; i < 6; i++)
                a4[i] = *(const float4*)(Ah + i * 36 + k4 * 4);
            #pragma unroll
            for (int kk = 0; kk < 4; kk++) {
                int k = k4 * 4 + kk;
                ulonglong2 bA = *(const ulonglong2*)(BwA + k * 64);
                ulonglong2 bB = *(const ulonglong2*)(BwB + k * 64);
                #pragma unroll
                for (int i = 0; i < 6; i++) {
                    unsigned long long aa = pk((&a4[i].x)[kk]);
                    fma2(acc[i][0], aa, bA.x);
                    fma2(acc[i][1], aa, bA.y);
                    fma2(acc[i][2], aa, bB.x);
                    fma2(acc[i][3], aa, bB.y);
                }
            }
        }
        // segments 1+2: k = 32..95 from g
        #pragma unroll 2
        for (int k4 = 0; k4 < 16; k4++) {
            float4 a4[6];
            #pragma unroll
            for (int i = 0; i < 6; i++)
                a4[i] = *(const float4*)(Ag + i * 68 + k4 * 4);
            #pragma unroll
            for (int kk = 0; kk < 4; kk++) {
                int k = 32 + k4 * 4 + kk;
                ulonglong2 bA = *(const ulonglong2*)(BwA + k * 64);
                ulonglong2 bB = *(const ulonglong2*)(BwB + k * 64);
                #pragma unroll
                for (int i = 0; i < 6; i++) {
                    unsigned long long aa = pk((&a4[i].x)[kk]);
                    fma2(acc[i][0], aa, bA.x);
                    fma2(acc[i][1], aa, bA.y);
                    fma2(acc[i][2], aa, bB.x);
                    fma2(acc[i][3], aa, bB.y);
                }
            }
        }
        __syncthreads();   // all reads of h1/g/w2 complete

        // store h2 (relu)
        #pragma unroll
        for (int i = 0; i < 6; i++) {
            float* dst = sm + S_H2 + (rg * 6 + i) * 68;
            float4 v0, v1;
            unpk(acc[i][0], v0.x, v0.y);
            unpk(acc[i][1], v0.z, v0.w);
            unpk(acc[i][2], v1.x, v1.y);
            unpk(acc[i][3], v1.z, v1.w);
            v0.x = fmaxf(v0.x, 0.f); v0.y = fmaxf(v0.y, 0.f);
            v0.z = fmaxf(v0.z, 0.f); v0.w = fmaxf(v0.w, 0.f);
            v1.x = fmaxf(v1.x, 0.f); v1.y = fmaxf(v1.y, 0.f);
            v1.z = fmaxf(v1.z, 0.f); v1.w = fmaxf(v1.w, 0.f);
            *(float4*)(dst + cg * 4)      = v0;
            *(float4*)(dst + 32 + cg * 4) = v1;
        }
    }

    // deferred FW1/FW2 load into the (now dead) h1 region (contiguous)
    {
        const float4* f1v = (const float4*)(fw1 + (size_t)l * 8192);
        const float4* f2v = (const float4*)(fw2 + (size_t)l * 4096);
        #pragma unroll
        for (int j = 0; j < 6; j++) {
            int i = tid + j * NTHREADS;        // 0..3071
            float4 v = (i < 2048) ? f1v[i] : f2v[i - 2048];
            *(float4*)(sm + S_FW1 + i * 4) = v;
        }
    }
    __syncthreads();

    // ------------------------------------------------------------------
    // Pool: pooled[32][128] = [mean(64) | max(64)] over 12 sites
    // ------------------------------------------------------------------
    #pragma unroll
    for (int p = 0; p < (BT * 64) / NTHREADS; p++) {
        int idx = tid + p * NTHREADS;
        int bt = idx >> 6;
        int o  = idx & 63;
        const float* q = sm + S_H2 + bt * 12 * 68 + o;
        float v0 = q[0];
        float sum = v0, mx = v0;
        #pragma unroll
        for (int s = 1; s < 12; s++) {
            float v = q[s * 68];
            sum += v;
            mx = fmaxf(mx, v);
        }
        sm[S_POOL + bt * 128 + o]      = sum * (1.0f / 12.0f);
        sm[S_POOL + bt * 128 + 64 + o] = mx;
    }
    __syncthreads();

    // ------------------------------------------------------------------
    // fc1 (128->64) + relu : thread = (bt = tid>>4, 4 outputs oq*4..+3)
    // ------------------------------------------------------------------
    {
        const int bt = tid >> 4;         // 0..31
        const int oq = tid & 15;         // 0..15
        float4 b4 = *(const float4*)(sm + S_FB1 + oq * 4);
        unsigned long long acc0 = pk2(b4.x, b4.y);
        unsigned long long acc1 = pk2(b4.z, b4.w);
        const float4* pool4 = (const float4*)(sm + S_POOL + bt * 128);
        #pragma unroll 8
        for (int f4 = 0; f4 < 32; f4++) {
            float4 p4 = pool4[f4];
            #pragma unroll
            for (int kk = 0; kk < 4; kk++) {
                int f = f4 * 4 + kk;
                ulonglong2 w = *(const ulonglong2*)(sm + S_FW1 + f * 64 + oq * 4);
                unsigned long long aa = pk((&p4.x)[kk]);
                fma2(acc0, aa, w.x);
                fma2(acc1, aa, w.y);
            }
        }
        float4 v;
        unpk(acc0, v.x, v.y);
        unpk(acc1, v.z, v.w);
        v.x = fmaxf(v.x, 0.f); v.y = fmaxf(v.y, 0.f);
        v.z = fmaxf(v.z, 0.f); v.w = fmaxf(v.w, 0.f);
        __syncthreads();   // pool reads of h2 done before F1 overwrites that region
        *(float4*)(sm + S_F1 + bt * 68 + oq * 4) = v;
    }
    __syncthreads();

    // fc2 (64->64) + relu
    {
        const int bt = tid >> 4;
        const int oq = tid & 15;
        float4 b4 = *(const float4*)(sm + S_FB2 + oq * 4);
        unsigned long long acc0 = pk2(b4.x, b4.y);
        unsigned long long acc1 = pk2(b4.z, b4.w);
        const float4* f1r = (const float4*)(sm + S_F1 + bt * 68);
        #pragma unroll 8
        for (int k4 = 0; k4 < 16; k4++) {
            float4 p4 = f1r[k4];
            #pragma unroll
            for (int kk = 0; kk < 4; kk++) {
                int k = k4 * 4 + kk;
                ulonglong2 w = *(const ulonglong2*)(sm + S_FW2 + k * 64 + oq * 4);
                unsigned long long aa = pk((&p4.x)[kk]);
                fma2(acc0, aa, w.x);
                fma2(acc1, aa, w.y);
            }
        }
        float4 v;
        unpk(acc0, v.x, v.y);
        unpk(acc1, v.z, v.w);
        v.x = fmaxf(v.x, 0.f); v.y = fmaxf(v.y, 0.f);
        v.z = fmaxf(v.z, 0.f); v.w = fmaxf(v.w, 0.f);
        *(float4*)(sm + S_F2 + bt * 68 + oq * 4) = v;
    }
    __syncthreads();

    // fc3 (64->1), out is (B, L) row-major
    if (tid < BT) {
        const int bt = tid;
        const float4* f2 = (const float4*)(sm + S_F2 + bt * 68);
        const float4* w3 = (const float4*)(sm + S_FW3);
        float acc = sm[S_FB3];
        #pragma unroll
        for (int k4 = 0; k4 < 16; k4++) {
            float4 a = f2[k4], b = w3[k4];
            acc += a.x * b.x + a.y * b.y + a.z * b.z + a.w * b.w;
        }
        out[(size_t)(b0 + bt) * LAYERS + l] = acc;
    }
}

extern "C" void kernel_launch(void* const* d_in, const int* in_sizes, int n_in,
                              void* d_out, int out_size)
{
    (void)in_sizes; (void)n_in; (void)out_size;
    const float* zs  = (const float*)d_in[0];
    const float* w1  = (const float*)d_in[1];
    const float* w2  = (const float*)d_in[2];
    const float* fw1 = (const float*)d_in[3];
    const float* fb1 = (const float*)d_in[4];
    const float* fw2 = (const float*)d_in[5];
    const float* fb2 = (const float*)d_in[6];
    const float* fw3 = (const float*)d_in[7];
    const float* fb3 = (const float*)d_in[8];
    float* out = (float*)d_out;

    static bool attr_set = false;
    if (!attr_set) {
        cudaFuncSetAttribute(twelve_sites_kernel,
                             cudaFuncAttributeMaxDynamicSharedMemorySize,
                             SMEM_BYTES);
        attr_set = true;
    }

    dim3 grid(BATCH / BT, LAYERS);   // (64, 63)
    twelve_sites_kernel<<<grid, NTHREADS, SMEM_BYTES>>>(
        zs, w1, w2, fw1, fb1, fw2, fb2, fw3, fb3, out);
}

// round 4
// speedup vs baseline: 1.6294x; 1.0040x over previous
#include <cuda_runtime.h>
#include <math.h>

// Problem constants
#define LAYERS 63
#define BATCH  2048
#define BT     16          // batch elements per tile
#define TILES  8           // tiles per CTA
#define NTHREADS 256
#define ROWS   (BT * 12)   // 192

// ---------------- shared memory layout (floats) ----------------
// persistent across tiles:
#define S_W1    0          // 192
#define S_FB1   192        // 64
#define S_FB2   256        // 64
#define S_FW3   320        // 64
#define S_FB3   384        // 1 (pad to 400)
#define S_ZS0   400        // 16*24 = 384
#define S_ZS1   784        // 384 -> 1168 (pad to 1184)
#define S_H1    1184       // 192*36 = 6912 -> 8096
#define S_W2    8096       // 96*64 = 6144  -> 14240
#define S_G     14240      // 192*68 = 13056 -> 27296
#define SMEM_FLOATS 27296
#define SMEM_BYTES (SMEM_FLOATS * 4)     // 109,184 B -> 2 CTAs/SM

// per-tile aliases (regions dead at the point of use)
#define S_FW2   S_H1               // 4096 (h1 dead after GEMM)
#define S_POOL  (S_H1 + 4096)      // 16*130 = 2080 -> 7360 <= 8096
#define S_FW1   S_G                // 8192 (h2 dead after pool)
#define S_F1    (S_G + 8192)       // 16*68 = 1088
#define S_F2    (S_G + 8192 + 1088) // 1088 -> 24608 <= 27296

// packed dual-fp32 FMA (Blackwell FFMA2)
__device__ __forceinline__ void fma2(unsigned long long& d,
                                     unsigned long long a,
                                     unsigned long long b) {
    asm("fma.rn.f32x2 %0, %1, %2, %0;" : "+l"(d) : "l"(a), "l"(b));
}
__device__ __forceinline__ unsigned long long add2(unsigned long long a,
                                                   unsigned long long b) {
    unsigned long long r;
    asm("add.rn.f32x2 %0, %1, %2;" : "=l"(r) : "l"(a), "l"(b));
    return r;
}
__device__ __forceinline__ unsigned long long pk(float a) {
    unsigned long long r;
    asm("mov.b64 %0, {%1, %1};" : "=l"(r) : "f"(a));
    return r;
}
__device__ __forceinline__ unsigned long long pk2(float lo, float hi) {
    unsigned long long r;
    asm("mov.b64 %0, {%1, %2};" : "=l"(r) : "f"(lo), "f"(hi));
    return r;
}
__device__ __forceinline__ void unpk(unsigned long long v, float& lo, float& hi) {
    asm("mov.b64 {%0, %1}, %2;" : "=f"(lo), "=f"(hi) : "l"(v));
}

__global__ void __launch_bounds__(NTHREADS, 2)
twelve_sites_kernel(const float* __restrict__ zs,
                    const float* __restrict__ w1,
                    const float* __restrict__ w2,
                    const float* __restrict__ fw1,
                    const float* __restrict__ fb1,
                    const float* __restrict__ fw2,
                    const float* __restrict__ fb2,
                    const float* __restrict__ fw3,
                    const float* __restrict__ fb3,
                    float* __restrict__ out)
{
    extern __shared__ float sm[];
    const int l   = blockIdx.y;
    const int bg  = blockIdx.x;              // batch group: 128 batch elems
    const int b0g = bg * (BT * TILES);
    const int tid = threadIdx.x;

    // ---------------- persistent weight load (once per CTA) ----------------
    for (int i = tid; i < 192; i += NTHREADS) sm[S_W1 + i] = w1[l * 192 + i];
    {
        const float4* w2v = (const float4*)(w2 + (size_t)l * 6144);
        for (int i = tid; i < 1536; i += NTHREADS)
            *(float4*)(sm + S_W2 + i * 4) = w2v[i];
    }
    if (tid < 64) {
        sm[S_FB1 + tid] = fb1[l * 64 + tid];
        sm[S_FB2 + tid] = fb2[l * 64 + tid];
        sm[S_FW3 + tid] = fw3[l * 64 + tid];
    }
    if (tid == 0) sm[S_FB3] = fb3[l];
    // zs tile 0 -> buf0
    if (tid < 96) {
        int i = tid / 6, j = tid % 6;
        *(float4*)(sm + S_ZS0 + i * 24 + j * 4) =
            *(const float4*)(zs + ((size_t)(b0g + i) * LAYERS + l) * 24 + j * 4);
    }
    __syncthreads();

    const float4* fw1v = (const float4*)(fw1 + (size_t)l * 8192);
    const float4* fw2v = (const float4*)(fw2 + (size_t)l * 4096);

    for (int t = 0; t < TILES; t++) {
        const int b0 = b0g + t * BT;
        const float* zbuf = sm + ((t & 1) ? S_ZS1 : S_ZS0);
        float* zbuf_next  = sm + ((t & 1) ? S_ZS0 : S_ZS1);

        // prefetch next tile's zs into registers
        float4 zreg;
        const bool zpre = (t + 1 < TILES) && (tid < 96);
        if (zpre) {
            int i = tid / 6, j = tid % 6;
            zreg = *(const float4*)(zs + ((size_t)(b0 + BT + i) * LAYERS + l) * 24 + j * 4);
        }

        // ---------------- Phase A: CNN1 -> h1[192][36] ----------------
        if (tid < ROWS) {
            const int r  = tid;
            const int bt = r / 12;
            const int s  = r % 12;
            const float* xz = zbuf + bt * 24;
            const int sp1 = (s + 1) % 12, sm1 = (s + 11) % 12;
            const int sp2 = (s + 2) % 12, sm2 = (s + 10) % 12;
            const int sp3 = (s + 3) % 12, sm3 = (s + 9) % 12;
            const int sp4 = (s + 4) % 12, sm4 = (s + 8) % 12;
            float a0 = xz[s * 2 + 0];
            float a1 = xz[s * 2 + 1];
            float a2 = xz[sp1*2]   + xz[sm1*2]   + xz[sp3*2]   + xz[sm3*2];
            float a3 = xz[sp1*2+1] + xz[sm1*2+1] + xz[sp3*2+1] + xz[sm3*2+1];
            float a4 = xz[sp2*2]   + xz[sm2*2]   + xz[sp4*2]   + xz[sm4*2];
            float a5 = xz[sp2*2+1] + xz[sm2*2+1] + xz[sp4*2+1] + xz[sm4*2+1];
            float* hrow = sm + S_H1 + r * 36;
            const float4* W4 = (const float4*)(sm + S_W1);
            #pragma unroll
            for (int c4 = 0; c4 < 8; c4++) {
                float4 q0 = W4[c4],      q1 = W4[8 + c4],  q2 = W4[16 + c4];
                float4 q3 = W4[24 + c4], q4 = W4[32 + c4], q5 = W4[40 + c4];
                float4 v;
                v.x = fmaxf(a0*q0.x + a1*q1.x + a2*q2.x + a3*q3.x + a4*q4.x + a5*q5.x, 0.f);
                v.y = fmaxf(a0*q0.y + a1*q1.y + a2*q2.y + a3*q3.y + a4*q4.y + a5*q5.y, 0.f);
                v.z = fmaxf(a0*q0.z + a1*q1.z + a2*q2.z + a3*q3.z + a4*q4.z + a5*q5.z, 0.f);
                v.w = fmaxf(a0*q0.w + a1*q1.w + a2*q2.w + a3*q3.w + a4*q4.w + a5*q5.w, 0.f);
                *(float4*)(hrow + c4 * 4) = v;
            }
        }
        __syncthreads();   // (1)

        // ---------------- Phase A2: g[192][68] ----------------
        if (tid < ROWS) {
            const int r    = tid;
            const int s    = r % 12;
            const int base = r - s;
            const float4* hp1 = (const float4*)(sm + S_H1 + (base + (s + 1) % 12) * 36);
            const float4* hm1 = (const float4*)(sm + S_H1 + (base + (s + 11) % 12) * 36);
            const float4* hp2 = (const float4*)(sm + S_H1 + (base + (s + 2) % 12) * 36);
            const float4* hm2 = (const float4*)(sm + S_H1 + (base + (s + 10) % 12) * 36);
            const float4* hp3 = (const float4*)(sm + S_H1 + (base + (s + 3) % 12) * 36);
            const float4* hm3 = (const float4*)(sm + S_H1 + (base + (s + 9) % 12) * 36);
            const float4* hp4 = (const float4*)(sm + S_H1 + (base + (s + 4) % 12) * 36);
            const float4* hm4 = (const float4*)(sm + S_H1 + (base + (s + 8) % 12) * 36);
            float* grow = sm + S_G + r * 68;
            #pragma unroll
            for (int j4 = 0; j4 < 8; j4++) {
                float4 p1 = hp1[j4], m1 = hm1[j4], p3 = hp3[j4], m3 = hm3[j4];
                float4 p2 = hp2[j4], m2 = hm2[j4], p4 = hp4[j4], m4 = hm4[j4];
                float4 g1, g2;
                g1.x = p1.x + m1.x + p3.x + m3.x;  g1.y = p1.y + m1.y + p3.y + m3.y;
                g1.z = p1.z + m1.z + p3.z + m3.z;  g1.w = p1.w + m1.w + p3.w + m3.w;
                g2.x = p2.x + m2.x + p4.x + m4.x;  g2.y = p2.y + m2.y + p4.y + m4.y;
                g2.z = p2.z + m2.z + p4.z + m4.z;  g2.w = p2.w + m2.w + p4.w + m4.w;
                *(float4*)(grow + j4 * 4)      = g1;
                *(float4*)(grow + 32 + j4 * 4) = g2;
            }
        }
        __syncthreads();   // (2)

        // ---------------- Phase B: GEMM h2 = [h1|g] @ w2, relu ----------------
        const int rg = tid >> 3;     // 0..31, rows rg*6..+5
        const int cg = tid & 7;      // cols {cg*4..+3, 32+cg*4..+3}
        float4 w2r[4];               // FW2 register prefetch
        {
            const float* Ah  = sm + S_H1 + rg * 6 * 36;
            const float* Ag  = sm + S_G  + rg * 6 * 68;
            const float* BwA = sm + S_W2 + cg * 4;
            const float* BwB = sm + S_W2 + 32 + cg * 4;

            unsigned long long acc[6][4];
            #pragma unroll
            for (int i = 0; i < 6; i++)
                #pragma unroll
                for (int j = 0; j < 4; j++) acc[i][j] = 0ull;

            #pragma unroll 2
            for (int k4 = 0; k4 < 8; k4++) {
                float4 a4[6];
                #pragma unroll
                for (int i = 0; i < 6; i++)
                    a4[i] = *(const float4*)(Ah + i * 36 + k4 * 4);
                #pragma unroll
                for (int kk = 0; kk < 4; kk++) {
                    int k = k4 * 4 + kk;
                    ulonglong2 bA = *(const ulonglong2*)(BwA + k * 64);
                    ulonglong2 bB = *(const ulonglong2*)(BwB + k * 64);
                    #pragma unroll
                    for (int i = 0; i < 6; i++) {
                        unsigned long long aa = pk((&a4[i].x)[kk]);
                        fma2(acc[i][0], aa, bA.x);
                        fma2(acc[i][1], aa, bA.y);
                        fma2(acc[i][2], aa, bB.x);
                        fma2(acc[i][3], aa, bB.y);
                    }
                }
            }
            #pragma unroll 2
            for (int k4 = 0; k4 < 16; k4++) {
                float4 a4[6];
                #pragma unroll
                for (int i = 0; i < 6; i++)
                    a4[i] = *(const float4*)(Ag + i * 68 + k4 * 4);
                #pragma unroll
                for (int kk = 0; kk < 4; kk++) {
                    int k = 32 + k4 * 4 + kk;
                    ulonglong2 bA = *(const ulonglong2*)(BwA + k * 64);
                    ulonglong2 bB = *(const ulonglong2*)(BwB + k * 64);
                    #pragma unroll
                    for (int i = 0; i < 6; i++) {
                        unsigned long long aa = pk((&a4[i].x)[kk]);
                        fma2(acc[i][0], aa, bA.x);
                        fma2(acc[i][1], aa, bA.y);
                        fma2(acc[i][2], aa, bB.x);
                        fma2(acc[i][3], aa, bB.y);
                    }
                }
            }

            // FW2 global prefetch (latency hidden behind store+pool)
            #pragma unroll
            for (int j = 0; j < 4; j++) w2r[j] = fw2v[tid + j * NTHREADS];

            __syncthreads();   // (3) all reads of h1/g done

            // store h2 (relu) into G
            #pragma unroll
            for (int i = 0; i < 6; i++) {
                float* dst = sm + S_G + (rg * 6 + i) * 68;
                float4 v0, v1;
                unpk(acc[i][0], v0.x, v0.y);
                unpk(acc[i][1], v0.z, v0.w);
                unpk(acc[i][2], v1.x, v1.y);
                unpk(acc[i][3], v1.z, v1.w);
                v0.x = fmaxf(v0.x, 0.f); v0.y = fmaxf(v0.y, 0.f);
                v0.z = fmaxf(v0.z, 0.f); v0.w = fmaxf(v0.w, 0.f);
                v1.x = fmaxf(v1.x, 0.f); v1.y = fmaxf(v1.y, 0.f);
                v1.z = fmaxf(v1.z, 0.f); v1.w = fmaxf(v1.w, 0.f);
                *(float4*)(dst + cg * 4)      = v0;
                *(float4*)(dst + 32 + cg * 4) = v1;
            }
        }

        // FW2 -> smem (h1 region dead), zs prefetch -> next buffer
        #pragma unroll
        for (int j = 0; j < 4; j++)
            *(float4*)(sm + S_FW2 + (tid + j * NTHREADS) * 4) = w2r[j];
        if (zpre) {
            int i = tid / 6, j = tid % 6;
            *(float4*)(zbuf_next + i * 24 + j * 4) = zreg;
        }

        // FW1 global prefetch (stored after pool)
        float4 w1r[8];
        #pragma unroll
        for (int j = 0; j < 8; j++) w1r[j] = fw1v[tid + j * NTHREADS];

        __syncthreads();   // (4) h2 visible

        // ---------------- Pool: pooled[16][130] = [mean|max] ----------------
        #pragma unroll
        for (int p = 0; p < (BT * 64) / NTHREADS; p++) {
            int idx = tid + p * NTHREADS;
            int bt = idx >> 6;
            int o  = idx & 63;
            const float* q = sm + S_G + bt * 12 * 68 + o;
            float v0 = q[0];
            float sum = v0, mx = v0;
            #pragma unroll
            for (int s = 1; s < 12; s++) {
                float v = q[s * 68];
                sum += v;
                mx = fmaxf(mx, v);
            }
            sm[S_POOL + bt * 130 + o]      = sum * (1.0f / 12.0f);
            sm[S_POOL + bt * 130 + 64 + o] = mx;
        }
        __syncthreads();   // (5) h2 dead

        // FW1 -> smem (G region)
        #pragma unroll
        for (int j = 0; j < 8; j++)
            *(float4*)(sm + S_FW1 + (tid + j * NTHREADS) * 4) = w1r[j];
        __syncthreads();   // (6)

        // ---------------- fc1 (128->64) + relu ----------------
        {
            const int oq = tid & 15;         // output quad
            const int bt = tid >> 4;         // 0..15
            float4 b4 = *(const float4*)(sm + S_FB1 + oq * 4);
            unsigned long long aA0 = pk2(b4.x, b4.y), aA1 = pk2(b4.z, b4.w);
            unsigned long long aB0 = 0ull, aB1 = 0ull;
            const float* poolr = sm + S_POOL + bt * 130;
            #pragma unroll 8
            for (int f = 0; f < 64; f++) {
                ulonglong2 wA = *(const ulonglong2*)(sm + S_FW1 + f * 64 + oq * 4);
                ulonglong2 wB = *(const ulonglong2*)(sm + S_FW1 + (f + 64) * 64 + oq * 4);
                unsigned long long pA = pk(poolr[f]);
                unsigned long long pB = pk(poolr[f + 64]);
                fma2(aA0, pA, wA.x);
                fma2(aA1, pA, wA.y);
                fma2(aB0, pB, wB.x);
                fma2(aB1, pB, wB.y);
            }
            unsigned long long s0 = add2(aA0, aB0), s1 = add2(aA1, aB1);
            float4 v;
            unpk(s0, v.x, v.y);
            unpk(s1, v.z, v.w);
            v.x = fmaxf(v.x, 0.f); v.y = fmaxf(v.y, 0.f);
            v.z = fmaxf(v.z, 0.f); v.w = fmaxf(v.w, 0.f);
            *(float4*)(sm + S_F1 + bt * 68 + oq * 4) = v;
        }
        __syncthreads();   // (7)

        // ---------------- fc2 (64->64) + relu ----------------
        {
            const int oq = tid & 15;
            const int bt = tid >> 4;
            float4 b4 = *(const float4*)(sm + S_FB2 + oq * 4);
            unsigned long long aA0 = pk2(b4.x, b4.y), aA1 = pk2(b4.z, b4.w);
            unsigned long long aB0 = 0ull, aB1 = 0ull;
            const float* f1r = sm + S_F1 + bt * 68;
            #pragma unroll 8
            for (int k = 0; k < 32; k++) {
                ulonglong2 wA = *(const ulonglong2*)(sm + S_FW2 + k * 64 + oq * 4);
                ulonglong2 wB = *(const ulonglong2*)(sm + S_FW2 + (k + 32) * 64 + oq * 4);
                unsigned long long pA = pk(f1r[k]);
                unsigned long long pB = pk(f1r[k + 32]);
                fma2(aA0, pA, wA.x);
                fma2(aA1, pA, wA.y);
                fma2(aB0, pB, wB.x);
                fma2(aB1, pB, wB.y);
            }
            unsigned long long s0 = add2(aA0, aB0), s1 = add2(aA1, aB1);
            float4 v;
            unpk(s0, v.x, v.y);
            unpk(s1, v.z, v.w);
            v.x = fmaxf(v.x, 0.f); v.y = fmaxf(v.y, 0.f);
            v.z = fmaxf(v.z, 0.f); v.w = fmaxf(v.w, 0.f);
            *(float4*)(sm + S_F2 + bt * 68 + oq * 4) = v;
        }
        __syncthreads();   // (8)

        // ---------------- fc3 (64->1) -> out (B, L) ----------------
        if (tid < BT) {
            const float4* f2 = (const float4*)(sm + S_F2 + tid * 68);
            const float4* w3 = (const float4*)(sm + S_FW3);
            float acc = sm[S_FB3];
            #pragma unroll
            for (int k4 = 0; k4 < 16; k4++) {
                float4 a = f2[k4], b = w3[k4];
                acc += a.x * b.x + a.y * b.y + a.z * b.z + a.w * b.w;
            }
            out[(size_t)(b0 + tid) * LAYERS + l] = acc;
        }
        // no sync needed here: next phase A writes only H1 (fc readers done at (8),
        // fc3 reads F2 in G which is next written at A2, after sync (1)).
    }
}

extern "C" void kernel_launch(void* const* d_in, const int* in_sizes, int n_in,
                              void* d_out, int out_size)
{
    (void)in_sizes; (void)n_in; (void)out_size;
    const float* zs  = (const float*)d_in[0];
    const float* w1  = (const float*)d_in[1];
    const float* w2  = (const float*)d_in[2];
    const float* fw1 = (const float*)d_in[3];
    const float* fb1 = (const float*)d_in[4];
    const float* fw2 = (const float*)d_in[5];
    const float* fb2 = (const float*)d_in[6];
    const float* fw3 = (const float*)d_in[7];
    const float* fb3 = (const float*)d_in[8];
    float* out = (float*)d_out;

    static bool attr_set = false;
    if (!attr_set) {
        cudaFuncSetAttribute(twelve_sites_kernel,
                             cudaFuncAttributeMaxDynamicSharedMemorySize,
                             SMEM_BYTES);
        attr_set = true;
    }

    dim3 grid(BATCH / (BT * TILES), LAYERS);   // (16, 63)
    twelve_sites_kernel<<<grid, NTHREADS, SMEM_BYTES>>>(
        zs, w1, w2, fw1, fb1, fw2, fb2, fw3, fb3, out);
}

// round 8
// speedup vs baseline: 2.7064x; 1.6610x over previous
#include <cuda_runtime.h>
#include <cstdint>
#include <math.h>

// Problem constants
#define LAYERS 63
#define BATCH  2048
#define BT     16          // batch elements per tile
#define TILES  8           // tiles per CTA
#define NTHREADS 256
#define ROWS   192

// ---------------- shared memory layout (floats) ----------------
#define S_W1    0          // 192
#define S_FB1   192        // 64
#define S_FB2   256        // 64
#define S_FW3   320        // 64
#define S_FB3   384        // 1 (pad to 400)
#define S_ZS0   400        // 384
#define S_ZS1   784        // 384 -> 1168 (pad 1184)
#define S_H1    1184       // 192*36 = 6912 -> 8096
#define S_G     8096       // 192*68 = 13056 -> 21152
#define S_W2    21152      // 96*72 = 6912 -> 28064   (tf32, stride 72)
#define S_FW1   28064      // 8192 -> 36256 (persistent)
#define S_FW2   36256      // 4096 -> 40352 (persistent)
#define S_POOL  40352      // 16*132 = 2112 -> 42464
#define S_F1    42464      // 16*68 = 1088 -> 43552
#define S_F2    43552      // 1088 -> 44640
#define SMEM_FLOATS 44640
#define SMEM_BYTES (SMEM_FLOATS * 4)   // 178,560 B

#define S_H2    S_G        // h2[192][68] aliases g after GEMM reads complete

// ---------------- helpers ----------------
__device__ __forceinline__ float to_tf32(float x) {
    uint32_t u;
    asm("cvt.rna.tf32.f32 %0, %1;" : "=r"(u) : "f"(x));
    return __uint_as_float(u);
}
__device__ __forceinline__ void mma_tf32(float* c,
                                         uint32_t a0, uint32_t a1, uint32_t a2, uint32_t a3,
                                         uint32_t b0, uint32_t b1) {
    asm volatile(
        "mma.sync.aligned.m16n8k8.row.col.f32.tf32.tf32.f32 "
        "{%0,%1,%2,%3}, {%4,%5,%6,%7}, {%8,%9}, {%0,%1,%2,%3};"
        : "+f"(c[0]), "+f"(c[1]), "+f"(c[2]), "+f"(c[3])
        : "r"(a0), "r"(a1), "r"(a2), "r"(a3), "r"(b0), "r"(b1));
}
__device__ __forceinline__ void fma2(unsigned long long& d,
                                     unsigned long long a,
                                     unsigned long long b) {
    asm("fma.rn.f32x2 %0, %1, %2, %0;" : "+l"(d) : "l"(a), "l"(b));
}
__device__ __forceinline__ unsigned long long pk(float a) {
    unsigned long long r;
    asm("mov.b64 %0, {%1, %1};" : "=l"(r) : "f"(a));
    return r;
}
__device__ __forceinline__ unsigned long long pk2(float lo, float hi) {
    unsigned long long r;
    asm("mov.b64 %0, {%1, %2};" : "=l"(r) : "f"(lo), "f"(hi));
    return r;
}
__device__ __forceinline__ void unpk(unsigned long long v, float& lo, float& hi) {
    asm("mov.b64 {%0, %1}, %2;" : "=f"(lo), "=f"(hi) : "l"(v));
}

__global__ void __launch_bounds__(NTHREADS, 1)
twelve_sites_kernel(const float* __restrict__ zs,
                    const float* __restrict__ w1,
                    const float* __restrict__ w2,
                    const float* __restrict__ fw1,
                    const float* __restrict__ fb1,
                    const float* __restrict__ fw2,
                    const float* __restrict__ fb2,
                    const float* __restrict__ fw3,
                    const float* __restrict__ fb3,
                    float* __restrict__ out)
{
    extern __shared__ float sm[];
    const int l   = blockIdx.y;
    const int bg  = blockIdx.x;
    const int b0g = bg * (BT * TILES);
    const int tid = threadIdx.x;
    const int wid = tid >> 5;
    const int lid = tid & 31;

    // ---------------- prologue: persistent loads ----------------
    for (int i = tid; i < 192; i += NTHREADS) sm[S_W1 + i] = w1[l * 192 + i];
    if (tid < 64) {
        sm[S_FB1 + tid] = fb1[l * 64 + tid];
        sm[S_FB2 + tid] = fb2[l * 64 + tid];
        sm[S_FW3 + tid] = fw3[l * 64 + tid];
    }
    if (tid == 0) sm[S_FB3] = fb3[l];
    {
        const float4* f1v = (const float4*)(fw1 + (size_t)l * 8192);
        #pragma unroll
        for (int j = 0; j < 8; j++)
            *(float4*)(sm + S_FW1 + (tid + j * NTHREADS) * 4) = f1v[tid + j * NTHREADS];
        const float4* f2v = (const float4*)(fw2 + (size_t)l * 4096);
        #pragma unroll
        for (int j = 0; j < 4; j++)
            *(float4*)(sm + S_FW2 + (tid + j * NTHREADS) * 4) = f2v[tid + j * NTHREADS];
    }
    // W2 (k-major [96][64]) -> smem stride 72, tf32-rounded
    for (int i = tid; i < 6144; i += NTHREADS) {
        int k = i >> 6, n = i & 63;
        sm[S_W2 + k * 72 + n] = to_tf32(w2[(size_t)l * 6144 + i]);
    }
    // zs tile 0
    if (tid < 96) {
        int i = tid / 6, j = tid % 6;
        *(float4*)(sm + S_ZS0 + i * 24 + j * 4) =
            *(const float4*)(zs + ((size_t)(b0g + i) * LAYERS + l) * 24 + j * 4);
    }
    __syncthreads();

    for (int t = 0; t < TILES; t++) {
        const int b0 = b0g + t * BT;
        const float* zbuf = sm + ((t & 1) ? S_ZS1 : S_ZS0);
        float* zbuf_next  = sm + ((t & 1) ? S_ZS0 : S_ZS1);

        // prefetch next zs tile
        float4 zreg;
        const bool zpre = (t + 1 < TILES) && (tid < 96);
        if (zpre) {
            int i = tid / 6, j = tid % 6;
            zreg = *(const float4*)(zs + ((size_t)(b0 + BT + i) * LAYERS + l) * 24 + j * 4);
        }

        // ---------------- Phase A: CNN1 -> h1[192][36] (tf32-rounded) ----------------
        if (tid < ROWS) {
            const int r  = tid;
            const int bt = r / 12;
            const int s  = r % 12;
            const float* xz = zbuf + bt * 24;
            const int sp1 = (s + 1) % 12, sm1 = (s + 11) % 12;
            const int sp2 = (s + 2) % 12, sm2 = (s + 10) % 12;
            const int sp3 = (s + 3) % 12, sm3 = (s + 9) % 12;
            const int sp4 = (s + 4) % 12, sm4 = (s + 8) % 12;
            float a0 = xz[s * 2 + 0];
            float a1 = xz[s * 2 + 1];
            float a2 = xz[sp1*2]   + xz[sm1*2]   + xz[sp3*2]   + xz[sm3*2];
            float a3 = xz[sp1*2+1] + xz[sm1*2+1] + xz[sp3*2+1] + xz[sm3*2+1];
            float a4 = xz[sp2*2]   + xz[sm2*2]   + xz[sp4*2]   + xz[sm4*2];
            float a5 = xz[sp2*2+1] + xz[sm2*2+1] + xz[sp4*2+1] + xz[sm4*2+1];
            float* hrow = sm + S_H1 + r * 36;
            const float4* W4 = (const float4*)(sm + S_W1);
            #pragma unroll
            for (int c4 = 0; c4 < 8; c4++) {
                float4 q0 = W4[c4],      q1 = W4[8 + c4],  q2 = W4[16 + c4];
                float4 q3 = W4[24 + c4], q4 = W4[32 + c4], q5 = W4[40 + c4];
                float4 v;
                v.x = to_tf32(fmaxf(a0*q0.x + a1*q1.x + a2*q2.x + a3*q3.x + a4*q4.x + a5*q5.x, 0.f));
                v.y = to_tf32(fmaxf(a0*q0.y + a1*q1.y + a2*q2.y + a3*q3.y + a4*q4.y + a5*q5.y, 0.f));
                v.z = to_tf32(fmaxf(a0*q0.z + a1*q1.z + a2*q2.z + a3*q3.z + a4*q4.z + a5*q5.z, 0.f));
                v.w = to_tf32(fmaxf(a0*q0.w + a1*q1.w + a2*q2.w + a3*q3.w + a4*q4.w + a5*q5.w, 0.f));
                *(float4*)(hrow + c4 * 4) = v;
            }
        }
        __syncthreads();   // (1)

        // ---------------- Phase A2: g[192][68] (tf32-rounded sums) ----------------
        if (tid < ROWS) {
            const int r    = tid;
            const int s    = r % 12;
            const int base = r - s;
            const float4* hp1 = (const float4*)(sm + S_H1 + (base + (s + 1) % 12) * 36);
            const float4* hm1 = (const float4*)(sm + S_H1 + (base + (s + 11) % 12) * 36);
            const float4* hp2 = (const float4*)(sm + S_H1 + (base + (s + 2) % 12) * 36);
            const float4* hm2 = (const float4*)(sm + S_H1 + (base + (s + 10) % 12) * 36);
            const float4* hp3 = (const float4*)(sm + S_H1 + (base + (s + 3) % 12) * 36);
            const float4* hm3 = (const float4*)(sm + S_H1 + (base + (s + 9) % 12) * 36);
            const float4* hp4 = (const float4*)(sm + S_H1 + (base + (s + 4) % 12) * 36);
            const float4* hm4 = (const float4*)(sm + S_H1 + (base + (s + 8) % 12) * 36);
            float* grow = sm + S_G + r * 68;
            #pragma unroll
            for (int j4 = 0; j4 < 8; j4++) {
                float4 p1 = hp1[j4], m1 = hm1[j4], p3 = hp3[j4], m3 = hm3[j4];
                float4 p2 = hp2[j4], m2 = hm2[j4], p4 = hp4[j4], m4 = hm4[j4];
                float4 g1, g2;
                g1.x = to_tf32(p1.x + m1.x + p3.x + m3.x);
                g1.y = to_tf32(p1.y + m1.y + p3.y + m3.y);
                g1.z = to_tf32(p1.z + m1.z + p3.z + m3.z);
                g1.w = to_tf32(p1.w + m1.w + p3.w + m3.w);
                g2.x = to_tf32(p2.x + m2.x + p4.x + m4.x);
                g2.y = to_tf32(p2.y + m2.y + p4.y + m4.y);
                g2.z = to_tf32(p2.z + m2.z + p4.z + m4.z);
                g2.w = to_tf32(p2.w + m2.w + p4.w + m4.w);
                *(float4*)(grow + j4 * 4)      = g1;
                *(float4*)(grow + 32 + j4 * 4) = g2;
            }
        }
        if (zpre) {
            int i = tid / 6, j = tid % 6;
            *(float4*)(zbuf_next + i * 24 + j * 4) = zreg;
        }
        __syncthreads();   // (2)

        // ---------------- Phase B: tf32 mma.sync GEMM ----------------
        // warp = 48 rows x 32 cols: 3 m16-tiles x 4 n8-tiles x 12 k-steps
        {
            const int mrow = (wid >> 1) * 48;
            const int nb   = (wid & 1) * 32;
            const int gid  = lid >> 2;   // 0..7
            const int tg   = lid & 3;    // 0..3

            float acc[3][4][4];
            #pragma unroll
            for (int mt = 0; mt < 3; mt++)
                #pragma unroll
                for (int nt = 0; nt < 4; nt++)
                    #pragma unroll
                    for (int q = 0; q < 4; q++) acc[mt][nt][q] = 0.f;

            #pragma unroll
            for (int ks = 0; ks < 12; ks++) {
                // B fragments (k = ks*8 + tg, +4; n = nb + nt*8 + gid)
                const float* Bk0 = sm + S_W2 + (ks * 8 + tg) * 72 + nb + gid;
                const float* Bk1 = Bk0 + 4 * 72;
                uint32_t b0[4], b1[4];
                #pragma unroll
                for (int nt = 0; nt < 4; nt++) {
                    b0[nt] = __float_as_uint(Bk0[nt * 8]);
                    b1[nt] = __float_as_uint(Bk1[nt * 8]);
                }
                #pragma unroll
                for (int mt = 0; mt < 3; mt++) {
                    const int r = mrow + mt * 16 + gid;
                    uint32_t a0, a1, a2, a3;
                    if (ks < 4) {
                        const float* Ar  = sm + S_H1 + r * 36 + ks * 8 + tg;
                        const float* Ar8 = Ar + 8 * 36;
                        a0 = __float_as_uint(Ar[0]);
                        a2 = __float_as_uint(Ar[4]);
                        a1 = __float_as_uint(Ar8[0]);
                        a3 = __float_as_uint(Ar8[4]);
                    } else {
                        const float* Ar  = sm + S_G + r * 68 + (ks - 4) * 8 + tg;
                        const float* Ar8 = Ar + 8 * 68;
                        a0 = __float_as_uint(Ar[0]);
                        a2 = __float_as_uint(Ar[4]);
                        a1 = __float_as_uint(Ar8[0]);
                        a3 = __float_as_uint(Ar8[4]);
                    }
                    #pragma unroll
                    for (int nt = 0; nt < 4; nt++)
                        mma_tf32(acc[mt][nt], a0, a1, a2, a3, b0[nt], b1[nt]);
                }
            }
            __syncthreads();   // (3) all reads of h1/g complete

            // store h2 (relu) into g region; D frag: rows gid/gid+8, cols tg*2,tg*2+1
            #pragma unroll
            for (int mt = 0; mt < 3; mt++) {
                const int r0 = mrow + mt * 16 + gid;
                #pragma unroll
                for (int nt = 0; nt < 4; nt++) {
                    const int cc = nb + nt * 8 + tg * 2;
                    float2 v0, v1;
                    v0.x = fmaxf(acc[mt][nt][0], 0.f);
                    v0.y = fmaxf(acc[mt][nt][1], 0.f);
                    v1.x = fmaxf(acc[mt][nt][2], 0.f);
                    v1.y = fmaxf(acc[mt][nt][3], 0.f);
                    *(float2*)(sm + S_H2 + r0 * 68 + cc)       = v0;
                    *(float2*)(sm + S_H2 + (r0 + 8) * 68 + cc) = v1;
                }
            }
        }
        __syncthreads();   // (4) h2 visible

        // ---------------- Pool: pooled[16][132] = [mean|max] ----------------
        #pragma unroll
        for (int p = 0; p < (BT * 64) / NTHREADS; p++) {
            int idx = tid + p * NTHREADS;
            int bt = idx >> 6;
            int o  = idx & 63;
            const float* q = sm + S_H2 + bt * 12 * 68 + o;
            float v0 = q[0];
            float sum = v0, mx = v0;
            #pragma unroll
            for (int s = 1; s < 12; s++) {
                float v = q[s * 68];
                sum += v;
                mx = fmaxf(mx, v);
            }
            sm[S_POOL + bt * 132 + o]      = sum * (1.0f / 12.0f);
            sm[S_POOL + bt * 132 + 64 + o] = mx;
        }
        __syncthreads();   // (5)

        // ---------------- fc1 (128->64) + relu ----------------
        {
            const int bt = tid & 15;
            const int oq = tid >> 4;     // 0..15
            float4 b4 = *(const float4*)(sm + S_FB1 + oq * 4);
            unsigned long long acc0 = pk2(b4.x, b4.y);
            unsigned long long acc1 = pk2(b4.z, b4.w);
            const float4* pool4 = (const float4*)(sm + S_POOL + bt * 132);
            #pragma unroll 8
            for (int f4 = 0; f4 < 32; f4++) {
                float4 p4 = pool4[f4];
                #pragma unroll
                for (int kk = 0; kk < 4; kk++) {
                    ulonglong2 w = *(const ulonglong2*)(sm + S_FW1 + (f4 * 4 + kk) * 64 + oq * 4);
                    unsigned long long aa = pk((&p4.x)[kk]);
                    fma2(acc0, aa, w.x);
                    fma2(acc1, aa, w.y);
                }
            }
            float4 v;
            unpk(acc0, v.x, v.y);
            unpk(acc1, v.z, v.w);
            v.x = fmaxf(v.x, 0.f); v.y = fmaxf(v.y, 0.f);
            v.z = fmaxf(v.z, 0.f); v.w = fmaxf(v.w, 0.f);
            *(float4*)(sm + S_F1 + bt * 68 + oq * 4) = v;
        }
        __syncthreads();   // (6)

        // ---------------- fc2 (64->64) + relu ----------------
        {
            const int bt = tid & 15;
            const int oq = tid >> 4;
            float4 b4 = *(const float4*)(sm + S_FB2 + oq * 4);
            unsigned long long acc0 = pk2(b4.x, b4.y);
            unsigned long long acc1 = pk2(b4.z, b4.w);
            const float4* f1r = (const float4*)(sm + S_F1 + bt * 68);
            #pragma unroll 8
            for (int k4 = 0; k4 < 16; k4++) {
                float4 p4 = f1r[k4];
                #pragma unroll
                for (int kk = 0; kk < 4; kk++) {
                    ulonglong2 w = *(const ulonglong2*)(sm + S_FW2 + (k4 * 4 + kk) * 64 + oq * 4);
                    unsigned long long aa = pk((&p4.x)[kk]);
                    fma2(acc0, aa, w.x);
                    fma2(acc1, aa, w.y);
                }
            }
            float4 v;
            unpk(acc0, v.x, v.y);
            unpk(acc1, v.z, v.w);
            v.x = fmaxf(v.x, 0.f); v.y = fmaxf(v.y, 0.f);
            v.z = fmaxf(v.z, 0.f); v.w = fmaxf(v.w, 0.f);
            *(float4*)(sm + S_F2 + bt * 68 + oq * 4) = v;
        }
        __syncthreads();   // (7)

        // ---------------- fc3 (64->1) -> out (B, L) ----------------
        if (tid < BT) {
            const float4* f2 = (const float4*)(sm + S_F2 + tid * 68);
            const float4* w3 = (const float4*)(sm + S_FW3);
            float acc = sm[S_FB3];
            #pragma unroll
            for (int k4 = 0; k4 < 16; k4++) {
                float4 a = f2[k4], b = w3[k4];
                acc += a.x * b.x + a.y * b.y + a.z * b.z + a.w * b.w;
            }
            out[(size_t)(b0 + tid) * LAYERS + l] = acc;
        }
        // next phase A writes only h1 (last read at sync (3));
        // A2 writes g=h2 (last read at sync (5)); all threads have passed both.
    }
}

extern "C" void kernel_launch(void* const* d_in, const int* in_sizes, int n_in,
                              void* d_out, int out_size)
{
    (void)in_sizes; (void)n_in; (void)out_size;
    const float* zs  = (const float*)d_in[0];
    const float* w1  = (const float*)d_in[1];
    const float* w2  = (const float*)d_in[2];
    const float* fw1 = (const float*)d_in[3];
    const float* fb1 = (const float*)d_in[4];
    const float* fw2 = (const float*)d_in[5];
    const float* fb2 = (const float*)d_in[6];
    const float* fw3 = (const float*)d_in[7];
    const float* fb3 = (const float*)d_in[8];
    float* out = (float*)d_out;

    static bool attr_set = false;
    if (!attr_set) {
        cudaFuncSetAttribute(twelve_sites_kernel,
                             cudaFuncAttributeMaxDynamicSharedMemorySize,
                             SMEM_BYTES);
        attr_set = true;
    }

    dim3 grid(BATCH / (BT * TILES), LAYERS);   // (16, 63)
    twelve_sites_kernel<<<grid, NTHREADS, SMEM_BYTES>>>(
        zs, w1, w2, fw1, fb1, fw2, fb2, fw3, fb3, out);
}

// round 9
// speedup vs baseline: 3.1849x; 1.1768x over previous
#include <cuda_runtime.h>
#include <cstdint>
#include <math.h>

// Problem constants
#define LAYERS 63
#define BATCH  2048
#define BT     32          // batch elements per tile
#define TILES  4           // tiles per CTA
#define NTHREADS 512
#define ROWS   (BT * 12)   // 384

// ---------------- shared memory layout (floats) ----------------
#define S_W1    0          // 192
#define S_FB1   192        // 64
#define S_FB2   256        // 64
#define S_FW3   320        // 64
#define S_FB3   384        // 1 (pad to 400)
#define S_ZS0   400        // 32*24 = 768
#define S_ZS1   1168       // 768 -> 1936 (pad 1952)
#define S_H1    1952       // 384*36 = 13824 -> 15776
#define S_G     15776      // 384*68 = 26112 -> 41888
#define S_W2    41888      // 96*72 = 6912 -> 48800 (tf32, stride 72)
#define SMEM_FLOATS 48800
#define SMEM_BYTES (SMEM_FLOATS * 4)   // 195,200 B

// aliases into dead regions
#define S_POOL  S_H1               // 32*129 = 4128  (h1 dead after GEMM)
#define S_FW1   (S_H1 + 4128)      // 8192 -> 12320 <= 13824
#define S_H2    S_G                // h2[384][68]
#define S_FW2   S_G                // 4096           (h2 dead after pool)
#define S_F1    (S_G + 4096)       // 32*65 = 2080
#define S_F2    (S_G + 6176)       // 2080 -> 8256 <= 26112

// ---------------- helpers ----------------
__device__ __forceinline__ float to_tf32(float x) {
    uint32_t u;
    asm("cvt.rna.tf32.f32 %0, %1;" : "=r"(u) : "f"(x));
    return __uint_as_float(u);
}
__device__ __forceinline__ void mma_tf32(float* c,
                                         uint32_t a0, uint32_t a1, uint32_t a2, uint32_t a3,
                                         uint32_t b0, uint32_t b1) {
    asm volatile(
        "mma.sync.aligned.m16n8k8.row.col.f32.tf32.tf32.f32 "
        "{%0,%1,%2,%3}, {%4,%5,%6,%7}, {%8,%9}, {%0,%1,%2,%3};"
        : "+f"(c[0]), "+f"(c[1]), "+f"(c[2]), "+f"(c[3])
        : "r"(a0), "r"(a1), "r"(a2), "r"(a3), "r"(b0), "r"(b1));
}
__device__ __forceinline__ void fma2(unsigned long long& d,
                                     unsigned long long a,
                                     unsigned long long b) {
    asm("fma.rn.f32x2 %0, %1, %2, %0;" : "+l"(d) : "l"(a), "l"(b));
}
__device__ __forceinline__ unsigned long long pk(float a) {
    unsigned long long r;
    asm("mov.b64 %0, {%1, %1};" : "=l"(r) : "f"(a));
    return r;
}
__device__ __forceinline__ unsigned long long pk2(float lo, float hi) {
    unsigned long long r;
    asm("mov.b64 %0, {%1, %2};" : "=l"(r) : "f"(lo), "f"(hi));
    return r;
}
__device__ __forceinline__ void unpk(unsigned long long v, float& lo, float& hi) {
    asm("mov.b64 {%0, %1}, %2;" : "=f"(lo), "=f"(hi) : "l"(v));
}

__global__ void __launch_bounds__(NTHREADS, 1)
twelve_sites_kernel(const float* __restrict__ zs,
                    const float* __restrict__ w1,
                    const float* __restrict__ w2,
                    const float* __restrict__ fw1,
                    const float* __restrict__ fb1,
                    const float* __restrict__ fw2,
                    const float* __restrict__ fb2,
                    const float* __restrict__ fw3,
                    const float* __restrict__ fb3,
                    float* __restrict__ out)
{
    extern __shared__ float sm[];
    const int l   = blockIdx.y;
    const int bg  = blockIdx.x;
    const int b0g = bg * (BT * TILES);
    const int tid = threadIdx.x;
    const int wid = tid >> 5;
    const int lid = tid & 31;

    // ---------------- prologue ----------------
    for (int i = tid; i < 192; i += NTHREADS) sm[S_W1 + i] = w1[l * 192 + i];
    if (tid < 64) {
        sm[S_FB1 + tid] = fb1[l * 64 + tid];
        sm[S_FB2 + tid] = fb2[l * 64 + tid];
        sm[S_FW3 + tid] = fw3[l * 64 + tid];
    }
    if (tid == 0) sm[S_FB3] = fb3[l];
    // W2 (k-major [96][64]) -> smem stride 72, tf32-rounded
    for (int i = tid; i < 6144; i += NTHREADS) {
        int k = i >> 6, n = i & 63;
        sm[S_W2 + k * 72 + n] = to_tf32(w2[(size_t)l * 6144 + i]);
    }
    // zs tile 0
    if (tid < 192) {
        int i = tid / 6, j = tid % 6;
        *(float4*)(sm + S_ZS0 + i * 24 + j * 4) =
            *(const float4*)(zs + ((size_t)(b0g + i) * LAYERS + l) * 24 + j * 4);
    }
    __syncthreads();

    const float4* fw1v = (const float4*)(fw1 + (size_t)l * 8192);
    const float4* fw2v = (const float4*)(fw2 + (size_t)l * 4096);

    for (int t = 0; t < TILES; t++) {
        const int b0 = b0g + t * BT;
        const float* zbuf = sm + ((t & 1) ? S_ZS1 : S_ZS0);
        float* zbuf_next  = sm + ((t & 1) ? S_ZS0 : S_ZS1);

        // prefetch next zs tile
        float4 zreg;
        const bool zpre = (t + 1 < TILES) && (tid < 192);
        if (zpre) {
            int i = tid / 6, j = tid % 6;
            zreg = *(const float4*)(zs + ((size_t)(b0 + BT + i) * LAYERS + l) * 24 + j * 4);
        }

        // ---------------- Phase A: CNN1 -> h1[384][36] (tf32-rounded) ----------------
        if (tid < ROWS) {
            const int r  = tid;
            const int bt = r / 12;
            const int s  = r % 12;
            const float* xz = zbuf + bt * 24;
            const int sp1 = (s + 1) % 12, sm1 = (s + 11) % 12;
            const int sp2 = (s + 2) % 12, sm2 = (s + 10) % 12;
            const int sp3 = (s + 3) % 12, sm3 = (s + 9) % 12;
            const int sp4 = (s + 4) % 12, sm4 = (s + 8) % 12;
            float a0 = xz[s * 2 + 0];
            float a1 = xz[s * 2 + 1];
            float a2 = xz[sp1*2]   + xz[sm1*2]   + xz[sp3*2]   + xz[sm3*2];
            float a3 = xz[sp1*2+1] + xz[sm1*2+1] + xz[sp3*2+1] + xz[sm3*2+1];
            float a4 = xz[sp2*2]   + xz[sm2*2]   + xz[sp4*2]   + xz[sm4*2];
            float a5 = xz[sp2*2+1] + xz[sm2*2+1] + xz[sp4*2+1] + xz[sm4*2+1];
            float* hrow = sm + S_H1 + r * 36;
            const float4* W4 = (const float4*)(sm + S_W1);
            #pragma unroll
            for (int c4 = 0; c4 < 8; c4++) {
                float4 q0 = W4[c4],      q1 = W4[8 + c4],  q2 = W4[16 + c4];
                float4 q3 = W4[24 + c4], q4 = W4[32 + c4], q5 = W4[40 + c4];
                float4 v;
                v.x = to_tf32(fmaxf(a0*q0.x + a1*q1.x + a2*q2.x + a3*q3.x + a4*q4.x + a5*q5.x, 0.f));
                v.y = to_tf32(fmaxf(a0*q0.y + a1*q1.y + a2*q2.y + a3*q3.y + a4*q4.y + a5*q5.y, 0.f));
                v.z = to_tf32(fmaxf(a0*q0.z + a1*q1.z + a2*q2.z + a3*q3.z + a4*q4.z + a5*q5.z, 0.f));
                v.w = to_tf32(fmaxf(a0*q0.w + a1*q1.w + a2*q2.w + a3*q3.w + a4*q4.w + a5*q5.w, 0.f));
                *(float4*)(hrow + c4 * 4) = v;
            }
        }
        __syncthreads();   // (1)

        // ---------------- Phase A2: g[384][68] (12-load scheme) ----------------
        if (tid < 256) {
            const int bt = tid >> 3;     // 0..31
            const int j4 = tid & 7;      // column quad
            const float* hb = sm + S_H1 + bt * 12 * 36 + j4 * 4;
            float4 h[12];
            #pragma unroll
            for (int s = 0; s < 12; s++)
                h[s] = *(const float4*)(hb + s * 36);
            float* gb = sm + S_G + bt * 12 * 68 + j4 * 4;
            #pragma unroll
            for (int s = 0; s < 12; s++) {
                float4 p1 = h[(s+1)%12], m1 = h[(s+11)%12], p3 = h[(s+3)%12], m3 = h[(s+9)%12];
                float4 p2 = h[(s+2)%12], m2 = h[(s+10)%12], p4 = h[(s+4)%12], m4 = h[(s+8)%12];
                float4 g1, g2;
                g1.x = to_tf32(p1.x + m1.x + p3.x + m3.x);
                g1.y = to_tf32(p1.y + m1.y + p3.y + m3.y);
                g1.z = to_tf32(p1.z + m1.z + p3.z + m3.z);
                g1.w = to_tf32(p1.w + m1.w + p3.w + m3.w);
                g2.x = to_tf32(p2.x + m2.x + p4.x + m4.x);
                g2.y = to_tf32(p2.y + m2.y + p4.y + m4.y);
                g2.z = to_tf32(p2.z + m2.z + p4.z + m4.z);
                g2.w = to_tf32(p2.w + m2.w + p4.w + m4.w);
                *(float4*)(gb + s * 68)      = g1;
                *(float4*)(gb + s * 68 + 32) = g2;
            }
        }
        if (zpre) {
            int i = tid / 6, j = tid % 6;
            *(float4*)(zbuf_next + i * 24 + j * 4) = zreg;
        }
        __syncthreads();   // (2)

        // ---------------- Phase B: tf32 mma.sync GEMM ----------------
        // 16 warps: warp = 48 rows x 32 cols (3 m16 x 4 n8 x 12 k-steps)
        float4 w1r[4];
        float4 w2r[2];
        {
            const int mrow = (wid >> 1) * 48;
            const int nb   = (wid & 1) * 32;
            const int gid  = lid >> 2;   // 0..7
            const int tg   = lid & 3;    // 0..3

            float acc[3][4][4];
            #pragma unroll
            for (int mt = 0; mt < 3; mt++)
                #pragma unroll
                for (int nt = 0; nt < 4; nt++)
                    #pragma unroll
                    for (int q = 0; q < 4; q++) acc[mt][nt][q] = 0.f;

            #pragma unroll
            for (int ks = 0; ks < 12; ks++) {
                const float* Bk0 = sm + S_W2 + (ks * 8 + tg) * 72 + nb + gid;
                const float* Bk1 = Bk0 + 4 * 72;
                uint32_t b0[4], b1[4];
                #pragma unroll
                for (int nt = 0; nt < 4; nt++) {
                    b0[nt] = __float_as_uint(Bk0[nt * 8]);
                    b1[nt] = __float_as_uint(Bk1[nt * 8]);
                }
                #pragma unroll
                for (int mt = 0; mt < 3; mt++) {
                    const int r = mrow + mt * 16 + gid;
                    uint32_t a0, a1, a2, a3;
                    if (ks < 4) {
                        const float* Ar  = sm + S_H1 + r * 36 + ks * 8 + tg;
                        const float* Ar8 = Ar + 8 * 36;
                        a0 = __float_as_uint(Ar[0]);
                        a2 = __float_as_uint(Ar[4]);
                        a1 = __float_as_uint(Ar8[0]);
                        a3 = __float_as_uint(Ar8[4]);
                    } else {
                        const float* Ar  = sm + S_G + r * 68 + (ks - 4) * 8 + tg;
                        const float* Ar8 = Ar + 8 * 68;
                        a0 = __float_as_uint(Ar[0]);
                        a2 = __float_as_uint(Ar[4]);
                        a1 = __float_as_uint(Ar8[0]);
                        a3 = __float_as_uint(Ar8[4]);
                    }
                    #pragma unroll
                    for (int nt = 0; nt < 4; nt++)
                        mma_tf32(acc[mt][nt], a0, a1, a2, a3, b0[nt], b1[nt]);
                }
            }
            __syncthreads();   // (3) all reads of h1/g complete

            // store h2 (relu) into g region
            #pragma unroll
            for (int mt = 0; mt < 3; mt++) {
                const int r0 = mrow + mt * 16 + gid;
                #pragma unroll
                for (int nt = 0; nt < 4; nt++) {
                    const int cc = nb + nt * 8 + tg * 2;
                    float2 v0, v1;
                    v0.x = fmaxf(acc[mt][nt][0], 0.f);
                    v0.y = fmaxf(acc[mt][nt][1], 0.f);
                    v1.x = fmaxf(acc[mt][nt][2], 0.f);
                    v1.y = fmaxf(acc[mt][nt][3], 0.f);
                    *(float2*)(sm + S_H2 + r0 * 68 + cc)       = v0;
                    *(float2*)(sm + S_H2 + (r0 + 8) * 68 + cc) = v1;
                }
            }
        }

        // FW1/FW2 global prefetch (acc registers now dead; latency hidden by pool)
        #pragma unroll
        for (int j = 0; j < 4; j++) w1r[j] = fw1v[tid + j * NTHREADS];
        #pragma unroll
        for (int j = 0; j < 2; j++) w2r[j] = fw2v[tid + j * NTHREADS];

        __syncthreads();   // (4) h2 visible, h1 fully dead

        // FW1 -> smem (h1 region, disjoint from pool)
        #pragma unroll
        for (int j = 0; j < 4; j++)
            *(float4*)(sm + S_FW1 + (tid + j * NTHREADS) * 4) = w1r[j];

        // ---------------- Pool: pooled[32][129] = [mean|max] ----------------
        #pragma unroll
        for (int p = 0; p < (BT * 64) / NTHREADS; p++) {
            int idx = tid + p * NTHREADS;
            int bt = idx >> 6;
            int o  = idx & 63;
            const float* q = sm + S_H2 + bt * 12 * 68 + o;
            float v0 = q[0];
            float sum = v0, mx = v0;
            #pragma unroll
            for (int s = 1; s < 12; s++) {
                float v = q[s * 68];
                sum += v;
                mx = fmaxf(mx, v);
            }
            sm[S_POOL + bt * 129 + o]      = sum * (1.0f / 12.0f);
            sm[S_POOL + bt * 129 + 64 + o] = mx;
        }
        __syncthreads();   // (5) h2 dead

        // FW2 -> smem (h2/G region)
        #pragma unroll
        for (int j = 0; j < 2; j++)
            *(float4*)(sm + S_FW2 + (tid + j * NTHREADS) * 4) = w2r[j];

        // ---------------- fc1 (128->64) + relu. warp = oq, lane = bt ----------------
        {
            const int bt = lid;          // 0..31
            const int oq = wid;          // 0..15
            float4 b4 = *(const float4*)(sm + S_FB1 + oq * 4);
            unsigned long long acc0 = pk2(b4.x, b4.y);
            unsigned long long acc1 = pk2(b4.z, b4.w);
            const float* pr = sm + S_POOL + bt * 129;
            #pragma unroll 8
            for (int f = 0; f < 128; f++) {
                ulonglong2 w = *(const ulonglong2*)(sm + S_FW1 + f * 64 + oq * 4);
                unsigned long long aa = pk(pr[f]);
                fma2(acc0, aa, w.x);
                fma2(acc1, aa, w.y);
            }
            float v0, v1, v2, v3;
            unpk(acc0, v0, v1);
            unpk(acc1, v2, v3);
            float* dst = sm + S_F1 + bt * 65 + oq * 4;
            dst[0] = fmaxf(v0, 0.f);
            dst[1] = fmaxf(v1, 0.f);
            dst[2] = fmaxf(v2, 0.f);
            dst[3] = fmaxf(v3, 0.f);
        }
        __syncthreads();   // (6)

        // ---------------- fc2 (64->64) + relu ----------------
        {
            const int bt = lid;
            const int oq = wid;
            float4 b4 = *(const float4*)(sm + S_FB2 + oq * 4);
            unsigned long long acc0 = pk2(b4.x, b4.y);
            unsigned long long acc1 = pk2(b4.z, b4.w);
            const float* pr = sm + S_F1 + bt * 65;
            #pragma unroll 8
            for (int k = 0; k < 64; k++) {
                ulonglong2 w = *(const ulonglong2*)(sm + S_FW2 + k * 64 + oq * 4);
                unsigned long long aa = pk(pr[k]);
                fma2(acc0, aa, w.x);
                fma2(acc1, aa, w.y);
            }
            float v0, v1, v2, v3;
            unpk(acc0, v0, v1);
            unpk(acc1, v2, v3);
            float* dst = sm + S_F2 + bt * 65 + oq * 4;
            dst[0] = fmaxf(v0, 0.f);
            dst[1] = fmaxf(v1, 0.f);
            dst[2] = fmaxf(v2, 0.f);
            dst[3] = fmaxf(v3, 0.f);
        }
        __syncthreads();   // (7)

        // ---------------- fc3 (64->1) -> out (B, L) ----------------
        if (tid < BT) {
            const float* f2 = sm + S_F2 + tid * 65;
            const float* w3 = sm + S_FW3;
            float acc = sm[S_FB3];
            #pragma unroll
            for (int k = 0; k < 64; k++) acc += f2[k] * w3[k];
            out[(size_t)(b0 + tid) * LAYERS + l] = acc;
        }
        // next phase A writes only h1 (pool/FW1 there are dead after fc1, sync (6));
        // A2 writes G (FW2/F1/F2 dead after fc2/fc3; A2 is after next sync (1)).
    }
}

extern "C" void kernel_launch(void* const* d_in, const int* in_sizes, int n_in,
                              void* d_out, int out_size)
{
    (void)in_sizes; (void)n_in; (void)out_size;
    const float* zs  = (const float*)d_in[0];
    const float* w1  = (const float*)d_in[1];
    const float* w2  = (const float*)d_in[2];
    const float* fw1 = (const float*)d_in[3];
    const float* fb1 = (const float*)d_in[4];
    const float* fw2 = (const float*)d_in[5];
    const float* fb2 = (const float*)d_in[6];
    const float* fw3 = (const float*)d_in[7];
    const float* fb3 = (const float*)d_in[8];
    float* out = (float*)d_out;

    static bool attr_set = false;
    if (!attr_set) {
        cudaFuncSetAttribute(twelve_sites_kernel,
                             cudaFuncAttributeMaxDynamicSharedMemorySize,
                             SMEM_BYTES);
        attr_set = true;
    }

    dim3 grid(BATCH / (BT * TILES), LAYERS);   // (16, 63)
    twelve_sites_kernel<<<grid, NTHREADS, SMEM_BYTES>>>(
        zs, w1, w2, fw1, fb1, fw2, fb2, fw3, fb3, out);
}